// round 1
// baseline (speedup 1.0000x reference)
#include <cuda_runtime.h>

#define M_Q   256
#define N_X   50000
#define DIM   3072
#define KCONST 750.0f
#define TOPK  16

#define INF_F __int_as_float(0x7f800000)

// Scratch (no allocations allowed in kernel_launch -> device globals)
__device__ float g_wmax;
__device__ float g_scores[M_Q * N_X];   // 51.2 MB
__device__ int   g_topk[M_Q * TOPK];

// ---------------------------------------------------------------------------
// Kernel 0: max(w) over 50000 elements, single CTA
// ---------------------------------------------------------------------------
__global__ __launch_bounds__(256) void k_wmax(const float* __restrict__ w, int n)
{
    __shared__ float sm[256];
    float v = -INF_F;
    for (int i = threadIdx.x; i < n; i += 256) v = fmaxf(v, w[i]);
    sm[threadIdx.x] = v;
    __syncthreads();
    for (int s = 128; s > 0; s >>= 1) {
        if (threadIdx.x < s) sm[threadIdx.x] = fmaxf(sm[threadIdx.x], sm[threadIdx.x + s]);
        __syncthreads();
    }
    if (threadIdx.x == 0) g_wmax = sm[0];
}

// ---------------------------------------------------------------------------
// Kernel 1: scoring GEMM.
// score[i,j] = |X_j|^2 + w'_j^2 - 2 * dot(X_tilde_i, X_j)
// CTA tile 128(M) x 128(N), thread tile 8x8, K chunk 8, fp32 exact.
// Column sum-of-squares fused into the same pass (no extra read of X).
// ---------------------------------------------------------------------------
#define TM  128
#define TN  128
#define KCH 8

__global__ __launch_bounds__(256, 1) void k_score(
    const float* __restrict__ Xt, const float* __restrict__ X,
    const float* __restrict__ w)
{
    __shared__ float As[KCH][TM];   // [k][m]
    __shared__ float Bs[KCH][TN];   // [k][n]

    const int tid = threadIdx.x;
    const int tx  = tid & 15;       // n direction (16)
    const int ty  = tid >> 4;       // m direction (16)
    const int m0  = blockIdx.y * TM;
    const int n0  = blockIdx.x * TN;

    // cooperative load indices: 256 threads load 128x8 of A and B each chunk
    const int lr = tid >> 1;            // 0..127
    const int lk = (tid & 1) * 4;       // 0 or 4

    float acc[8][8];
    float bsq[8];
#pragma unroll
    for (int i = 0; i < 8; i++) {
        bsq[i] = 0.f;
#pragma unroll
        for (int j = 0; j < 8; j++) acc[i][j] = 0.f;
    }

    const int   gj_load = n0 + lr;
    const float* aptr = Xt + (size_t)(m0 + lr) * DIM + lk;
    const float* bptr = (gj_load < N_X) ? (X + (size_t)gj_load * DIM + lk) : 0;

    for (int k0 = 0; k0 < DIM; k0 += KCH) {
        float4 av = *(const float4*)(aptr + k0);
        float4 bv = bptr ? *(const float4*)(bptr + k0) : make_float4(0.f, 0.f, 0.f, 0.f);

        __syncthreads();   // protect previous iteration's shared reads
        As[lk + 0][lr] = av.x; As[lk + 1][lr] = av.y;
        As[lk + 2][lr] = av.z; As[lk + 3][lr] = av.w;
        Bs[lk + 0][lr] = bv.x; Bs[lk + 1][lr] = bv.y;
        Bs[lk + 2][lr] = bv.z; Bs[lk + 3][lr] = bv.w;
        __syncthreads();

#pragma unroll
        for (int kk = 0; kk < KCH; kk++) {
            float a[8], b[8];
            *(float4*)&a[0] = *(const float4*)&As[kk][ty * 8];
            *(float4*)&a[4] = *(const float4*)&As[kk][ty * 8 + 4];
            *(float4*)&b[0] = *(const float4*)&Bs[kk][tx * 8];
            *(float4*)&b[4] = *(const float4*)&Bs[kk][tx * 8 + 4];
#pragma unroll
            for (int j = 0; j < 8; j++) bsq[j] = fmaf(b[j], b[j], bsq[j]);
#pragma unroll
            for (int i = 0; i < 8; i++)
#pragma unroll
                for (int j = 0; j < 8; j++)
                    acc[i][j] = fmaf(a[i], b[j], acc[i][j]);
        }
    }

    const float wmax = g_wmax;
    float colterm[8];
#pragma unroll
    for (int j = 0; j < 8; j++) {
        int gj = n0 + tx * 8 + j;
        if (gj < N_X) {
            float wp = (wmax - w[gj]) * (1.0f / KCONST);
            colterm[j] = bsq[j] + wp * wp;
        } else {
            colterm[j] = 0.f;
        }
    }
#pragma unroll
    for (int i = 0; i < 8; i++) {
        int gm = m0 + ty * 8 + i;
#pragma unroll
        for (int j = 0; j < 8; j++) {
            int gj = n0 + tx * 8 + j;
            if (gj < N_X)
                g_scores[gm * N_X + gj] = colterm[j] - 2.0f * acc[i][j];
        }
    }
}

// ---------------------------------------------------------------------------
// Kernel 2: top-16 smallest scores per row (one CTA per row).
// Each thread keeps a private sorted top-16 over its strided slice, then
// 16 rounds of block-wide min selection over the 256*16 candidates.
// Ties broken toward smaller index (matches jax.lax.top_k determinism).
// ---------------------------------------------------------------------------
__global__ __launch_bounds__(256) void k_topk()
{
    __shared__ float sv[256 * TOPK];
    __shared__ int   si[256 * TOPK];
    __shared__ float rv[256];
    __shared__ int   rj[256];
    __shared__ int   rs[256];

    const int row = blockIdx.x;
    const int tid = threadIdx.x;

    float bv[TOPK]; int bi[TOPK];
#pragma unroll
    for (int t = 0; t < TOPK; t++) { bv[t] = INF_F; bi[t] = 0x7fffffff; }

    const float* srow = g_scores + row * N_X;
    for (int j = tid; j < N_X; j += 256) {
        float v = srow[j];
        if (v < bv[TOPK - 1]) {
            int p = TOPK - 1;
            while (p > 0 && bv[p - 1] > v) {
                bv[p] = bv[p - 1]; bi[p] = bi[p - 1]; p--;
            }
            bv[p] = v; bi[p] = j;
        }
    }
#pragma unroll
    for (int t = 0; t < TOPK; t++) {
        sv[tid * TOPK + t] = bv[t];
        si[tid * TOPK + t] = bi[t];
    }
    __syncthreads();

    for (int sel = 0; sel < TOPK; sel++) {
        float mv = INF_F; int mj = 0x7fffffff; int ms = 0;
#pragma unroll
        for (int t = 0; t < TOPK; t++) {
            int   idx = tid * TOPK + t;
            float v   = sv[idx];
            int   jj  = si[idx];
            if (v < mv || (v == mv && jj < mj)) { mv = v; mj = jj; ms = idx; }
        }
        rv[tid] = mv; rj[tid] = mj; rs[tid] = ms;
        __syncthreads();
        for (int s = 128; s > 0; s >>= 1) {
            if (tid < s) {
                if (rv[tid + s] < rv[tid] ||
                    (rv[tid + s] == rv[tid] && rj[tid + s] < rj[tid])) {
                    rv[tid] = rv[tid + s];
                    rj[tid] = rj[tid + s];
                    rs[tid] = rs[tid + s];
                }
            }
            __syncthreads();
        }
        if (tid == 0) {
            g_topk[row * TOPK + sel] = rj[0];
            sv[rs[0]] = INF_F;   // remove winner
        }
        __syncthreads();
    }
}

// ---------------------------------------------------------------------------
// Kernel 3: exact L1 re-rank over the 16 neighbors, max activation per row.
// ---------------------------------------------------------------------------
__global__ __launch_bounds__(128) void k_final(
    const float* __restrict__ Xt, const float* __restrict__ X,
    const float* __restrict__ w, float* __restrict__ out)
{
    __shared__ float4 xt4[DIM / 4];   // 12 KB query row
    __shared__ float  red[128];

    const int row = blockIdx.x;
    const int tid = threadIdx.x;

    const float4* xtg = (const float4*)(Xt + (size_t)row * DIM);
    for (int i = tid; i < DIM / 4; i += 128) xt4[i] = xtg[i];
    __syncthreads();

    float best = -INF_F;
    for (int t = 0; t < TOPK; t++) {
        int j = g_topk[row * TOPK + t];
        const float4* xg = (const float4*)(X + (size_t)j * DIM);
        float s = 0.f;
        for (int i = tid; i < DIM / 4; i += 128) {
            float4 xv = xg[i]; float4 tv = xt4[i];
            s += fabsf(xv.x - tv.x) + fabsf(xv.y - tv.y)
               + fabsf(xv.z - tv.z) + fabsf(xv.w - tv.w);
        }
        red[tid] = s;
        __syncthreads();
        for (int st = 64; st > 0; st >>= 1) {
            if (tid < st) red[tid] += red[tid + st];
            __syncthreads();
        }
        if (tid == 0) {
            float act = w[j] - KCONST * red[0];
            if (act > best) best = act;
        }
        __syncthreads();
    }
    if (tid == 0) out[row] = best;
}

// ---------------------------------------------------------------------------
extern "C" void kernel_launch(void* const* d_in, const int* in_sizes, int n_in,
                              void* d_out, int out_size)
{
    const float* Xt = (const float*)d_in[0];   // [256, 3072]
    const float* X  = (const float*)d_in[1];   // [50000, 3072]
    const float* w  = (const float*)d_in[2];   // [50000, 1]
    float* out = (float*)d_out;                // [256, 1]

    k_wmax<<<1, 256>>>(w, N_X);

    dim3 grid((N_X + TN - 1) / TN, M_Q / TM);  // (391, 2)
    k_score<<<grid, 256>>>(Xt, X, w);

    k_topk<<<M_Q, 256>>>();

    k_final<<<M_Q, 128>>>(Xt, X, w, out);
}

// round 2
// speedup vs baseline: 1.0066x; 1.0066x over previous
#include <cuda_runtime.h>

#define M_Q   256
#define N_X   50000
#define DIM   3072
#define KCONST 750.0f
#define TOPK  16

#define INF_F __int_as_float(0x7f800000)

// Scratch (no allocations allowed in kernel_launch -> device globals)
__device__ float g_wmax;
__device__ float g_scores[M_Q * N_X];   // 51.2 MB
__device__ int   g_topk[M_Q * TOPK];

// ---------------------------------------------------------------------------
// Kernel 0: max(w) over 50000 elements, single CTA
// ---------------------------------------------------------------------------
__global__ __launch_bounds__(256) void k_wmax(const float* __restrict__ w, int n)
{
    __shared__ float sm[256];
    float v = -INF_F;
    for (int i = threadIdx.x; i < n; i += 256) v = fmaxf(v, w[i]);
    sm[threadIdx.x] = v;
    __syncthreads();
    for (int s = 128; s > 0; s >>= 1) {
        if (threadIdx.x < s) sm[threadIdx.x] = fmaxf(sm[threadIdx.x], sm[threadIdx.x + s]);
        __syncthreads();
    }
    if (threadIdx.x == 0) g_wmax = sm[0];
}

// ---------------------------------------------------------------------------
// Kernel 1: scoring GEMM.
// score[i,j] = |X_j|^2 + w'_j^2 - 2 * dot(X_tilde_i, X_j)
// CTA tile 128(M) x 128(N), thread tile 8x8, K chunk 8, fp32 exact.
// Column sum-of-squares fused into the same pass (no extra read of X).
// ---------------------------------------------------------------------------
#define TM  128
#define TN  128
#define KCH 8

__global__ __launch_bounds__(256, 1) void k_score(
    const float* __restrict__ Xt, const float* __restrict__ X,
    const float* __restrict__ w)
{
    __shared__ float As[KCH][TM];   // [k][m]
    __shared__ float Bs[KCH][TN];   // [k][n]

    const int tid = threadIdx.x;
    const int tx  = tid & 15;       // n direction (16)
    const int ty  = tid >> 4;       // m direction (16)
    const int m0  = blockIdx.y * TM;
    const int n0  = blockIdx.x * TN;

    // cooperative load indices: 256 threads load 128x8 of A and B each chunk
    const int lr = tid >> 1;            // 0..127
    const int lk = (tid & 1) * 4;       // 0 or 4

    float acc[8][8];
    float bsq[8];
#pragma unroll
    for (int i = 0; i < 8; i++) {
        bsq[i] = 0.f;
#pragma unroll
        for (int j = 0; j < 8; j++) acc[i][j] = 0.f;
    }

    const int   gj_load = n0 + lr;
    const float* aptr = Xt + (size_t)(m0 + lr) * DIM + lk;
    const float* bptr = (gj_load < N_X) ? (X + (size_t)gj_load * DIM + lk) : 0;

    for (int k0 = 0; k0 < DIM; k0 += KCH) {
        float4 av = *(const float4*)(aptr + k0);
        float4 bv = bptr ? *(const float4*)(bptr + k0) : make_float4(0.f, 0.f, 0.f, 0.f);

        __syncthreads();   // protect previous iteration's shared reads
        As[lk + 0][lr] = av.x; As[lk + 1][lr] = av.y;
        As[lk + 2][lr] = av.z; As[lk + 3][lr] = av.w;
        Bs[lk + 0][lr] = bv.x; Bs[lk + 1][lr] = bv.y;
        Bs[lk + 2][lr] = bv.z; Bs[lk + 3][lr] = bv.w;
        __syncthreads();

#pragma unroll
        for (int kk = 0; kk < KCH; kk++) {
            float a[8], b[8];
            *(float4*)&a[0] = *(const float4*)&As[kk][ty * 8];
            *(float4*)&a[4] = *(const float4*)&As[kk][ty * 8 + 4];
            *(float4*)&b[0] = *(const float4*)&Bs[kk][tx * 8];
            *(float4*)&b[4] = *(const float4*)&Bs[kk][tx * 8 + 4];
#pragma unroll
            for (int j = 0; j < 8; j++) bsq[j] = fmaf(b[j], b[j], bsq[j]);
#pragma unroll
            for (int i = 0; i < 8; i++)
#pragma unroll
                for (int j = 0; j < 8; j++)
                    acc[i][j] = fmaf(a[i], b[j], acc[i][j]);
        }
    }

    const float wmax = g_wmax;
    float colterm[8];
#pragma unroll
    for (int j = 0; j < 8; j++) {
        int gj = n0 + tx * 8 + j;
        if (gj < N_X) {
            float wp = (wmax - w[gj]) * (1.0f / KCONST);
            colterm[j] = bsq[j] + wp * wp;
        } else {
            colterm[j] = 0.f;
        }
    }
#pragma unroll
    for (int i = 0; i < 8; i++) {
        int gm = m0 + ty * 8 + i;
#pragma unroll
        for (int j = 0; j < 8; j++) {
            int gj = n0 + tx * 8 + j;
            if (gj < N_X)
                g_scores[gm * N_X + gj] = colterm[j] - 2.0f * acc[i][j];
        }
    }
}

// ---------------------------------------------------------------------------
// Kernel 2: top-16 smallest scores per row (one CTA per row).
// Each thread keeps a private sorted top-16 over its strided slice, then
// 16 rounds of block-wide min selection over the 256*16 candidates.
// Ties broken toward smaller index (matches jax.lax.top_k determinism).
// ---------------------------------------------------------------------------
__global__ __launch_bounds__(256) void k_topk()
{
    __shared__ float sv[256 * TOPK];
    __shared__ int   si[256 * TOPK];
    __shared__ float rv[256];
    __shared__ int   rj[256];
    __shared__ int   rs[256];

    const int row = blockIdx.x;
    const int tid = threadIdx.x;

    float bv[TOPK]; int bi[TOPK];
#pragma unroll
    for (int t = 0; t < TOPK; t++) { bv[t] = INF_F; bi[t] = 0x7fffffff; }

    const float* srow = g_scores + row * N_X;
    for (int j = tid; j < N_X; j += 256) {
        float v = srow[j];
        if (v < bv[TOPK - 1]) {
            int p = TOPK - 1;
            while (p > 0 && bv[p - 1] > v) {
                bv[p] = bv[p - 1]; bi[p] = bi[p - 1]; p--;
            }
            bv[p] = v; bi[p] = j;
        }
    }
#pragma unroll
    for (int t = 0; t < TOPK; t++) {
        sv[tid * TOPK + t] = bv[t];
        si[tid * TOPK + t] = bi[t];
    }
    __syncthreads();

    for (int sel = 0; sel < TOPK; sel++) {
        float mv = INF_F; int mj = 0x7fffffff; int ms = 0;
#pragma unroll
        for (int t = 0; t < TOPK; t++) {
            int   idx = tid * TOPK + t;
            float v   = sv[idx];
            int   jj  = si[idx];
            if (v < mv || (v == mv && jj < mj)) { mv = v; mj = jj; ms = idx; }
        }
        rv[tid] = mv; rj[tid] = mj; rs[tid] = ms;
        __syncthreads();
        for (int s = 128; s > 0; s >>= 1) {
            if (tid < s) {
                if (rv[tid + s] < rv[tid] ||
                    (rv[tid + s] == rv[tid] && rj[tid + s] < rj[tid])) {
                    rv[tid] = rv[tid + s];
                    rj[tid] = rj[tid + s];
                    rs[tid] = rs[tid + s];
                }
            }
            __syncthreads();
        }
        if (tid == 0) {
            g_topk[row * TOPK + sel] = rj[0];
            sv[rs[0]] = INF_F;   // remove winner
        }
        __syncthreads();
    }
}

// ---------------------------------------------------------------------------
// Kernel 3: exact L1 re-rank over the 16 neighbors, max activation per row.
// ---------------------------------------------------------------------------
__global__ __launch_bounds__(128) void k_final(
    const float* __restrict__ Xt, const float* __restrict__ X,
    const float* __restrict__ w, float* __restrict__ out)
{
    __shared__ float4 xt4[DIM / 4];   // 12 KB query row
    __shared__ float  red[128];

    const int row = blockIdx.x;
    const int tid = threadIdx.x;

    const float4* xtg = (const float4*)(Xt + (size_t)row * DIM);
    for (int i = tid; i < DIM / 4; i += 128) xt4[i] = xtg[i];
    __syncthreads();

    float best = -INF_F;
    for (int t = 0; t < TOPK; t++) {
        int j = g_topk[row * TOPK + t];
        const float4* xg = (const float4*)(X + (size_t)j * DIM);
        float s = 0.f;
        for (int i = tid; i < DIM / 4; i += 128) {
            float4 xv = xg[i]; float4 tv = xt4[i];
            s += fabsf(xv.x - tv.x) + fabsf(xv.y - tv.y)
               + fabsf(xv.z - tv.z) + fabsf(xv.w - tv.w);
        }
        red[tid] = s;
        __syncthreads();
        for (int st = 64; st > 0; st >>= 1) {
            if (tid < st) red[tid] += red[tid + st];
            __syncthreads();
        }
        if (tid == 0) {
            float act = w[j] - KCONST * red[0];
            if (act > best) best = act;
        }
        __syncthreads();
    }
    if (tid == 0) out[row] = best;
}

// ---------------------------------------------------------------------------
extern "C" void kernel_launch(void* const* d_in, const int* in_sizes, int n_in,
                              void* d_out, int out_size)
{
    const float* Xt = (const float*)d_in[0];   // [256, 3072]
    const float* X  = (const float*)d_in[1];   // [50000, 3072]
    const float* w  = (const float*)d_in[2];   // [50000, 1]
    float* out = (float*)d_out;                // [256, 1]

    k_wmax<<<1, 256>>>(w, N_X);

    dim3 grid((N_X + TN - 1) / TN, M_Q / TM);  // (391, 2)
    k_score<<<grid, 256>>>(Xt, X, w);

    k_topk<<<M_Q, 256>>>();

    k_final<<<M_Q, 128>>>(Xt, X, w, out);
}

// round 4
// speedup vs baseline: 2.0816x; 2.0680x over previous
#include <cuda_runtime.h>
#include <cstdint>
#include <cstddef>

#define M_Q    256
#define N_X    50000
#define DIM    3072
#define KCONST 750.0f
#define TOPK   16

#define TILE_N  128
#define N_TILES 391            // ceil(50000/128)
#define KC      32             // k-chunk (floats)
#define CHUNKS  96             // 3072/32
#define A_BYTES (256*KC*4)     // 32 KB
#define B_BYTES (TILE_N*KC*4)  // 16 KB
#define STAGE   (A_BYTES + B_BYTES)   // 48 KB
#define CT_OFF  (3*STAGE)             // colterm after 3 stages
#define SMEM_TOTAL (CT_OFF + TILE_N*4)

#define INF_F __int_as_float(0x7f800000)

__device__ float g_wmax;
__device__ float g_scores[M_Q * N_X];   // 51.2 MB scratch
__device__ int   g_topk[M_Q * TOPK];
__device__ float g_act[M_Q * TOPK];

// ---------------- helpers ----------------
__device__ __forceinline__ uint32_t smem_u32(const void* p) {
    uint32_t a;
    asm("{ .reg .u64 t; cvta.to.shared.u64 t, %1; cvt.u32.u64 %0, t; }" : "=r"(a) : "l"(p));
    return a;
}
__device__ __forceinline__ void cp16(uint32_t dst, const void* src, uint32_t sz) {
    asm volatile("cp.async.cg.shared.global [%0], [%1], 16, %2;"
                 :: "r"(dst), "l"(src), "r"(sz) : "memory");
}
#define CP_COMMIT() asm volatile("cp.async.commit_group;" ::: "memory")
#define CP_WAIT1()  asm volatile("cp.async.wait_group 1;" ::: "memory")

// swizzled float index within a [rows][32-float] tile: 16B-unit XOR by row.
// Verified conflict-free for all m16n8k8 fragment access patterns.
__device__ __forceinline__ int sw_idx(int row, int k) {
    return row * 32 + ((((k >> 2) ^ (row & 7)) << 2) | (k & 3));
}

#define MMA_TF32(d, a, b)                                                      \
    asm volatile("mma.sync.aligned.m16n8k8.row.col.f32.tf32.tf32.f32 "        \
                 "{%0,%1,%2,%3}, {%4,%5,%6,%7}, {%8,%9}, {%0,%1,%2,%3};"      \
                 : "+f"((d)[0]), "+f"((d)[1]), "+f"((d)[2]), "+f"((d)[3])     \
                 : "r"((a)[0]), "r"((a)[1]), "r"((a)[2]), "r"((a)[3]),        \
                   "r"((b)[0]), "r"((b)[1]))

// ---------------- kernel 0: max(w) ----------------
__global__ __launch_bounds__(256) void k_wmax(const float* __restrict__ w, int n)
{
    __shared__ float sm[256];
    float v = -INF_F;
    for (int i = threadIdx.x; i < n; i += 256) v = fmaxf(v, w[i]);
    sm[threadIdx.x] = v;
    __syncthreads();
    for (int s = 128; s > 0; s >>= 1) {
        if (threadIdx.x < s) sm[threadIdx.x] = fmaxf(sm[threadIdx.x], sm[threadIdx.x + s]);
        __syncthreads();
    }
    if (threadIdx.x == 0) g_wmax = sm[0];
}

// ---------------- kernel 1: tf32 mma.sync scoring GEMM ----------------
// score[m,j] = |X_j|^2 + w'_j^2 - 2*dot(Xt_m, X_j)
// CTA: M=256 x N=128; 8 warps 4(M)x2(N), warp tile 64x64.
// 3-stage cp.async pipeline, k-chunk 32. |X_j|^2 fused from B fragments.
__device__ __forceinline__ void issue_chunk(
    uint32_t sb, int buf, int c, const float* __restrict__ Xt,
    const float* __restrict__ X, int n0, int tid)
{
    const int k0 = c * KC;
    const int u  = tid & 7;         // 16B unit within a 128B row
    const int rb = tid >> 3;        // 0..31
    const uint32_t ab = sb + buf * STAGE;
    const uint32_t bb = ab + A_BYTES;
#pragma unroll
    for (int i = 0; i < 8; i++) {   // A: 256 rows
        const int row = rb + 32 * i;
        cp16(ab + row * 128 + ((u ^ (row & 7)) << 4),
             Xt + (size_t)row * DIM + k0 + u * 4, 16u);
    }
#pragma unroll
    for (int i = 0; i < 4; i++) {   // B: 128 rows
        const int row = rb + 32 * i;
        const int gj  = n0 + row;
        const int gjc = gj < N_X ? gj : (N_X - 1);
        cp16(bb + row * 128 + ((u ^ (row & 7)) << 4),
             X + (size_t)gjc * DIM + k0 + u * 4, gj < N_X ? 16u : 0u);
    }
}

__global__ __launch_bounds__(256, 1) void k_score(
    const float* __restrict__ Xt, const float* __restrict__ X,
    const float* __restrict__ w)
{
    extern __shared__ char smem[];
    const uint32_t sb = smem_u32(smem);
    const int tid  = threadIdx.x;
    const int wid  = tid >> 5;
    const int lane = tid & 31;
    const int qr   = lane >> 2;     // 0..7
    const int qc   = lane & 3;      // 0..3
    const int wm   = wid >> 1;      // 0..3 -> m block of 64
    const int wn   = wid & 1;       // 0..1 -> n block of 64
    const int n0   = blockIdx.x * TILE_N;

    issue_chunk(sb, 0, 0, Xt, X, n0, tid); CP_COMMIT();
    issue_chunk(sb, 1, 1, Xt, X, n0, tid); CP_COMMIT();

    float acc[4][8][4];
#pragma unroll
    for (int mt = 0; mt < 4; mt++)
#pragma unroll
        for (int nt = 0; nt < 8; nt++)
#pragma unroll
            for (int q = 0; q < 4; q++) acc[mt][nt][q] = 0.f;
    float bsq[8];
#pragma unroll
    for (int nt = 0; nt < 8; nt++) bsq[nt] = 0.f;

    for (int c = 0; c < CHUNKS; c++) {
        CP_WAIT1();
        __syncthreads();
        if (c + 2 < CHUNKS) issue_chunk(sb, (c + 2) % 3, c + 2, Xt, X, n0, tid);
        CP_COMMIT();

        const float* Ab = (const float*)(smem + (c % 3) * STAGE);
        const float* Bb = (const float*)(smem + (c % 3) * STAGE + A_BYTES);

#pragma unroll
        for (int ks = 0; ks < 4; ks++) {
            const int kb = ks * 8;
            uint32_t b[8][2];
#pragma unroll
            for (int nt = 0; nt < 8; nt++) {
                const int br = wn * 64 + nt * 8 + qr;
                b[nt][0] = __float_as_uint(Bb[sw_idx(br, kb + qc)]);
                b[nt][1] = __float_as_uint(Bb[sw_idx(br, kb + qc + 4)]);
            }
            uint32_t a[4][4];
#pragma unroll
            for (int mt = 0; mt < 4; mt++) {
                const int ar = wm * 64 + mt * 16 + qr;
                a[mt][0] = __float_as_uint(Ab[sw_idx(ar,     kb + qc)]);
                a[mt][1] = __float_as_uint(Ab[sw_idx(ar + 8, kb + qc)]);
                a[mt][2] = __float_as_uint(Ab[sw_idx(ar,     kb + qc + 4)]);
                a[mt][3] = __float_as_uint(Ab[sw_idx(ar + 8, kb + qc + 4)]);
            }
            if (wm == 0) {
#pragma unroll
                for (int nt = 0; nt < 8; nt++) {
                    const float f0 = __uint_as_float(b[nt][0]);
                    const float f1 = __uint_as_float(b[nt][1]);
                    bsq[nt] = fmaf(f0, f0, fmaf(f1, f1, bsq[nt]));
                }
            }
#pragma unroll
            for (int mt = 0; mt < 4; mt++)
#pragma unroll
                for (int nt = 0; nt < 8; nt++)
                    MMA_TF32(acc[mt][nt], a[mt], b[nt]);
        }
    }

    // colterm = |X_j|^2 + w'_j^2 (warps 0,1 own all 128 cols via B frags)
    float* ct = (float*)(smem + CT_OFF);
    if (wm == 0) {
        const float wmax = g_wmax;
#pragma unroll
        for (int nt = 0; nt < 8; nt++) {
            float s = bsq[nt];
            s += __shfl_xor_sync(0xffffffffu, s, 1);
            s += __shfl_xor_sync(0xffffffffu, s, 2);
            if (qc == 0) {
                const int col = wn * 64 + nt * 8 + qr;
                const int j   = n0 + col;
                float v = INF_F;
                if (j < N_X) {
                    const float wp = (wmax - w[j]) * (1.f / KCONST);
                    v = s + wp * wp;
                }
                ct[col] = v;
            }
        }
    }
    __syncthreads();

    // epilogue: score = ct[col] - 2*dot, float2 stores
#pragma unroll
    for (int mt = 0; mt < 4; mt++) {
        const int r0 = wm * 64 + mt * 16 + qr;
#pragma unroll
        for (int nt = 0; nt < 8; nt++) {
            const int col = wn * 64 + nt * 8 + 2 * qc;
            const int j   = n0 + col;
            if (j < N_X) {   // j even, N_X even -> j+1 also valid
                const float c0 = ct[col], c1 = ct[col + 1];
                float2 v0 = { c0 - 2.f * acc[mt][nt][0], c1 - 2.f * acc[mt][nt][1] };
                float2 v1 = { c0 - 2.f * acc[mt][nt][2], c1 - 2.f * acc[mt][nt][3] };
                *(float2*)&g_scores[(size_t)r0 * N_X + j]       = v0;
                *(float2*)&g_scores[(size_t)(r0 + 8) * N_X + j] = v1;
            }
        }
    }
}

// ---------------- kernel 2: top-16 smallest per row ----------------
__global__ __launch_bounds__(256) void k_topk()
{
    __shared__ float sv[256 * TOPK];
    __shared__ int   si[256 * TOPK];
    __shared__ float rv[256];
    __shared__ int   rj[256];
    __shared__ int   rs[256];

    const int row = blockIdx.x, tid = threadIdx.x;
    float bv[TOPK]; int bi[TOPK];
#pragma unroll
    for (int t = 0; t < TOPK; t++) { bv[t] = INF_F; bi[t] = 0x7fffffff; }

    const float* srow = g_scores + (size_t)row * N_X;
    for (int j = tid; j < N_X; j += 256) {
        const float v = srow[j];
        if (v < bv[TOPK - 1]) {
            int p = TOPK - 1;
            while (p > 0 && bv[p - 1] > v) { bv[p] = bv[p-1]; bi[p] = bi[p-1]; p--; }
            bv[p] = v; bi[p] = j;
        }
    }
#pragma unroll
    for (int t = 0; t < TOPK; t++) { sv[tid*TOPK + t] = bv[t]; si[tid*TOPK + t] = bi[t]; }
    __syncthreads();

    for (int sel = 0; sel < TOPK; sel++) {
        float mv = INF_F; int mj = 0x7fffffff; int ms = 0;
#pragma unroll
        for (int t = 0; t < TOPK; t++) {
            const int idx = tid*TOPK + t;
            const float v = sv[idx]; const int jj = si[idx];
            if (v < mv || (v == mv && jj < mj)) { mv = v; mj = jj; ms = idx; }
        }
        rv[tid] = mv; rj[tid] = mj; rs[tid] = ms;
        __syncthreads();
        for (int s = 128; s > 0; s >>= 1) {
            if (tid < s) {
                if (rv[tid+s] < rv[tid] || (rv[tid+s] == rv[tid] && rj[tid+s] < rj[tid])) {
                    rv[tid] = rv[tid+s]; rj[tid] = rj[tid+s]; rs[tid] = rs[tid+s];
                }
            }
            __syncthreads();
        }
        if (tid == 0) { g_topk[row*TOPK + sel] = rj[0]; sv[rs[0]] = INF_F; }
        __syncthreads();
    }
}

// ---------------- kernel 3a: exact L1 activation per (row, neighbor) -------
__global__ __launch_bounds__(256) void k_l1(
    const float* __restrict__ Xt, const float* __restrict__ X,
    const float* __restrict__ w)
{
    const int gw   = blockIdx.x * 8 + (threadIdx.x >> 5);
    const int lane = threadIdx.x & 31;
    const int row  = gw >> 4;
    const int t    = gw & 15;
    const int j    = g_topk[row * TOPK + t];

    const float4* xa = (const float4*)(X  + (size_t)j   * DIM);
    const float4* xb = (const float4*)(Xt + (size_t)row * DIM);
    float s = 0.f;
#pragma unroll 4
    for (int i = lane; i < DIM / 4; i += 32) {
        const float4 a = xa[i], b = xb[i];
        s += fabsf(a.x-b.x) + fabsf(a.y-b.y) + fabsf(a.z-b.z) + fabsf(a.w-b.w);
    }
#pragma unroll
    for (int o = 16; o > 0; o >>= 1) s += __shfl_xor_sync(0xffffffffu, s, o);
    if (lane == 0) g_act[row * TOPK + t] = w[j] - KCONST * s;
}

// ---------------- kernel 3b: max over 16 activations --------------------
__global__ __launch_bounds__(256) void k_max(float* __restrict__ out)
{
    const int row = threadIdx.x;
    float best = -INF_F;
#pragma unroll
    for (int t = 0; t < TOPK; t++) best = fmaxf(best, g_act[row * TOPK + t]);
    out[row] = best;
}

// ---------------------------------------------------------------------------
extern "C" void kernel_launch(void* const* d_in, const int* in_sizes, int n_in,
                              void* d_out, int out_size)
{
    const float* Xt = (const float*)d_in[0];
    const float* X  = (const float*)d_in[1];
    const float* w  = (const float*)d_in[2];
    float* out = (float*)d_out;

    cudaFuncSetAttribute(k_score, cudaFuncAttributeMaxDynamicSharedMemorySize,
                         SMEM_TOTAL);

    k_wmax<<<1, 256>>>(w, N_X);
    k_score<<<N_TILES, 256, SMEM_TOTAL>>>(Xt, X, w);
    k_topk<<<M_Q, 256>>>();
    k_l1<<<(M_Q * TOPK) / 8, 256>>>(Xt, X, w);
    k_max<<<1, 256>>>(out);
}

// round 5
// speedup vs baseline: 5.9955x; 2.8803x over previous
#include <cuda_runtime.h>
#include <cuda_fp16.h>
#include <cstdint>
#include <cstddef>

#define M_Q    256
#define N_X    50000
#define DIM    3072
#define KCONST 750.0f
#define TOPK   16
#define NCAND  32

#define TILE_N  128
#define N_TILES 391              // ceil(50000/128)
#define KC      64               // k-chunk in halves (=128B rows)
#define CHUNKS  48               // 3072/64
#define A_BYTES (256*128)        // 32 KB
#define B_BYTES (128*128)        // 16 KB
#define STAGE   (A_BYTES + B_BYTES)
#define SMEM_TOTAL (3*STAGE)     // 144 KB

#define INF_F __int_as_float(0x7f800000)

// ---------------- device scratch ----------------
__device__ float  g_wmax;
__device__ __half g_Xh[(size_t)N_X * DIM];    // 307 MB f16 copy of X
__device__ __half g_Xth[M_Q * DIM];           // f16 copy of X_tilde
__device__ float  g_ct[N_X];                  // exact |X_j|^2 + w'_j^2
__device__ float  g_scores[(size_t)M_Q * N_X];
__device__ int    g_cand[M_Q * NCAND];
__device__ float  g_d2[M_Q * NCAND];
__device__ int    g_topk[M_Q * TOPK];
__device__ float  g_act[M_Q * TOPK];

// ---------------- helpers ----------------
__device__ __forceinline__ uint32_t smem_u32(const void* p) {
    uint32_t a;
    asm("{ .reg .u64 t; cvta.to.shared.u64 t, %1; cvt.u32.u64 %0, t; }" : "=r"(a) : "l"(p));
    return a;
}
__device__ __forceinline__ void cp16(uint32_t dst, const void* src, uint32_t sz) {
    asm volatile("cp.async.cg.shared.global [%0], [%1], 16, %2;"
                 :: "r"(dst), "l"(src), "r"(sz) : "memory");
}
#define CP_COMMIT() asm volatile("cp.async.commit_group;" ::: "memory")
#define CP_WAIT1()  asm volatile("cp.async.wait_group 1;" ::: "memory")

#define LDMATRIX_X4(r0, r1, r2, r3, addr)                                     \
    asm volatile("ldmatrix.sync.aligned.m8n8.x4.shared.b16 {%0,%1,%2,%3}, [%4];" \
                 : "=r"(r0), "=r"(r1), "=r"(r2), "=r"(r3) : "r"(addr))

#define MMA_F16(d, a, b)                                                       \
    asm volatile("mma.sync.aligned.m16n8k16.row.col.f32.f16.f16.f32 "          \
                 "{%0,%1,%2,%3}, {%4,%5,%6,%7}, {%8,%9}, {%0,%1,%2,%3};"       \
                 : "+f"((d)[0]), "+f"((d)[1]), "+f"((d)[2]), "+f"((d)[3])      \
                 : "r"((a)[0]), "r"((a)[1]), "r"((a)[2]), "r"((a)[3]),         \
                   "r"((b)[0]), "r"((b)[1]))

// ---------------- kernel 0: max(w) ----------------
__global__ __launch_bounds__(256) void k_wmax(const float* __restrict__ w, int n)
{
    __shared__ float sm[256];
    float v = -INF_F;
    for (int i = threadIdx.x; i < n; i += 256) v = fmaxf(v, w[i]);
    sm[threadIdx.x] = v;
    __syncthreads();
    for (int s = 128; s > 0; s >>= 1) {
        if (threadIdx.x < s) sm[threadIdx.x] = fmaxf(sm[threadIdx.x], sm[threadIdx.x + s]);
        __syncthreads();
    }
    if (threadIdx.x == 0) g_wmax = sm[0];
}

// ---------------- kernel 0b: fp32->f16 convert + exact col terms ----------
// One warp per row. Rows [0,N_X) = X -> g_Xh (+ g_ct); rows [N_X, N_X+M_Q) = Xt.
__global__ __launch_bounds__(256) void k_cvt(
    const float* __restrict__ Xt, const float* __restrict__ X,
    const float* __restrict__ w)
{
    const int warp = blockIdx.x * 8 + (threadIdx.x >> 5);
    const int lane = threadIdx.x & 31;
    if (warp >= N_X + M_Q) return;
    const bool isX = warp < N_X;
    const float4* src = (const float4*)(isX ? X + (size_t)warp * DIM
                                            : Xt + (size_t)(warp - N_X) * DIM);
    __half2* dst = (__half2*)(isX ? g_Xh + (size_t)warp * DIM
                                  : g_Xth + (size_t)(warp - N_X) * DIM);
    float bsq = 0.f;
    for (int i = lane; i < DIM / 4; i += 32) {
        const float4 v = src[i];
        bsq = fmaf(v.x, v.x, fmaf(v.y, v.y, fmaf(v.z, v.z, fmaf(v.w, v.w, bsq))));
        dst[2*i]   = __floats2half2_rn(v.x, v.y);
        dst[2*i+1] = __floats2half2_rn(v.z, v.w);
    }
    if (isX) {
#pragma unroll
        for (int o = 16; o > 0; o >>= 1) bsq += __shfl_xor_sync(0xffffffffu, bsq, o);
        if (lane == 0) {
            const float wp = (g_wmax - w[warp]) * (1.f / KCONST);
            g_ct[warp] = bsq + wp * wp;
        }
    }
}

// ---------------- kernel 1: f16 mma.sync scoring GEMM ----------------
// score[m,j] ~ ct[j] - 2*dot_f16(Xt_m, X_j). CTA: M=256 x N=128, 8 warps
// (4M x 2N), warp tile 64x64. k-chunk 64 halves, 3-stage cp.async, ldmatrix.
__device__ __forceinline__ void issue_chunk_h(uint32_t sb, int buf, int c,
                                              int n0, int tid)
{
    const int k0 = c * KC;
    const uint32_t ab = sb + buf * STAGE;
    const uint32_t bb = ab + A_BYTES;
#pragma unroll
    for (int i = 0; i < 8; i++) {                 // A: 2048 16B units
        const int uid = tid + 256 * i;
        const int row = uid >> 3, u = uid & 7;
        cp16(ab + row * 128 + (((u) ^ (row & 7)) << 4),
             g_Xth + (size_t)row * DIM + k0 + u * 8, 16u);
    }
#pragma unroll
    for (int i = 0; i < 4; i++) {                 // B: 1024 16B units
        const int uid = tid + 256 * i;
        const int row = uid >> 3, u = uid & 7;
        const int gj  = n0 + row;
        const int gjc = gj < N_X ? gj : (N_X - 1);
        cp16(bb + row * 128 + (((u) ^ (row & 7)) << 4),
             g_Xh + (size_t)gjc * DIM + k0 + u * 8, gj < N_X ? 16u : 0u);
    }
}

__global__ __launch_bounds__(256, 1) void k_score()
{
    extern __shared__ char smem[];
    const uint32_t sb = smem_u32(smem);
    const int tid  = threadIdx.x;
    const int wid  = tid >> 5;
    const int lane = tid & 31;
    const int qr   = lane >> 2;        // 0..7
    const int qc   = lane & 3;         // 0..3
    const int wm   = wid >> 1;         // 0..3
    const int wn   = wid & 1;          // 0..1
    const int n0   = blockIdx.x * TILE_N;

    // ldmatrix lane-address components
    const int sel = lane >> 3;         // 0..3
    const int rl  = lane & 7;
    const int rA  = ((sel & 1) << 3) + rl;    // A local row within 16
    const int uA  = sel >> 1;                  // A k-unit offset (0/1)
    const int rB  = ((sel >> 1) << 3) + rl;   // B local row within 16
    const int uB  = sel & 1;                   // B k-unit offset (0/1)

    issue_chunk_h(sb, 0, 0, n0, tid); CP_COMMIT();
    issue_chunk_h(sb, 1, 1, n0, tid); CP_COMMIT();

    float acc[4][8][4];
#pragma unroll
    for (int mt = 0; mt < 4; mt++)
#pragma unroll
        for (int nt = 0; nt < 8; nt++)
#pragma unroll
            for (int q = 0; q < 4; q++) acc[mt][nt][q] = 0.f;

    for (int c = 0; c < CHUNKS; c++) {
        CP_WAIT1();
        __syncthreads();
        if (c + 2 < CHUNKS) issue_chunk_h(sb, (c + 2) % 3, c + 2, n0, tid);
        CP_COMMIT();

        const uint32_t Ab = sb + (c % 3) * STAGE;
        const uint32_t Bb = Ab + A_BYTES;

#pragma unroll
        for (int ks = 0; ks < 4; ks++) {
            uint32_t a[4][4], b[8][2];
#pragma unroll
            for (int mt = 0; mt < 4; mt++) {
                const int row = wm * 64 + mt * 16 + rA;
                const uint32_t addr = Ab + row * 128 + (((ks*2 + uA) ^ rl) << 4);
                LDMATRIX_X4(a[mt][0], a[mt][1], a[mt][2], a[mt][3], addr);
            }
#pragma unroll
            for (int p = 0; p < 4; p++) {
                const int row = wn * 64 + p * 16 + rB;
                const uint32_t addr = Bb + row * 128 + (((ks*2 + uB) ^ rl) << 4);
                LDMATRIX_X4(b[2*p][0], b[2*p][1], b[2*p+1][0], b[2*p+1][1], addr);
            }
#pragma unroll
            for (int mt = 0; mt < 4; mt++)
#pragma unroll
                for (int nt = 0; nt < 8; nt++)
                    MMA_F16(acc[mt][nt], a[mt], b[nt]);
        }
    }

    // stage exact col terms to smem (reuse stage 0)
    __syncthreads();
    float* cts = (float*)smem;
    if (tid < TILE_N) {
        const int j = n0 + tid;
        cts[tid] = (j < N_X) ? g_ct[j] : INF_F;
    }
    __syncthreads();

#pragma unroll
    for (int mt = 0; mt < 4; mt++) {
        const int r0 = wm * 64 + mt * 16 + qr;
#pragma unroll
        for (int nt = 0; nt < 8; nt++) {
            const int col = wn * 64 + nt * 8 + 2 * qc;
            const int j   = n0 + col;
            if (j < N_X) {
                const float c0 = cts[col], c1 = cts[col + 1];
                float2 v0 = { c0 - 2.f * acc[mt][nt][0], c1 - 2.f * acc[mt][nt][1] };
                float2 v1 = { c0 - 2.f * acc[mt][nt][2], c1 - 2.f * acc[mt][nt][3] };
                *(float2*)&g_scores[(size_t)r0 * N_X + j]       = v0;
                *(float2*)&g_scores[(size_t)(r0 + 8) * N_X + j] = v1;
            }
        }
    }
}

// ---------------- kernel 2: approx top-32 candidates per row ----------------
#define PT 8
__global__ __launch_bounds__(256) void k_topk()
{
    __shared__ float sv[256 * PT];
    __shared__ int   si[256 * PT];
    __shared__ float rv[256];
    __shared__ int   rj[256];
    __shared__ int   rs[256];

    const int row = blockIdx.x, tid = threadIdx.x;
    float bv[PT]; int bi[PT];
#pragma unroll
    for (int t = 0; t < PT; t++) { bv[t] = INF_F; bi[t] = 0x7fffffff; }

    const float* srow = g_scores + (size_t)row * N_X;
    for (int j = tid; j < N_X; j += 256) {
        const float v = srow[j];
        if (v < bv[PT - 1]) {
            int p = PT - 1;
            while (p > 0 && bv[p - 1] > v) { bv[p] = bv[p-1]; bi[p] = bi[p-1]; p--; }
            bv[p] = v; bi[p] = j;
        }
    }
#pragma unroll
    for (int t = 0; t < PT; t++) { sv[tid*PT + t] = bv[t]; si[tid*PT + t] = bi[t]; }
    __syncthreads();

    for (int sel = 0; sel < NCAND; sel++) {
        float mv = INF_F; int mj = 0x7fffffff; int ms = 0;
#pragma unroll
        for (int t = 0; t < PT; t++) {
            const int idx = tid*PT + t;
            const float v = sv[idx]; const int jj = si[idx];
            if (v < mv || (v == mv && jj < mj)) { mv = v; mj = jj; ms = idx; }
        }
        rv[tid] = mv; rj[tid] = mj; rs[tid] = ms;
        __syncthreads();
        for (int s = 128; s > 0; s >>= 1) {
            if (tid < s) {
                if (rv[tid+s] < rv[tid] || (rv[tid+s] == rv[tid] && rj[tid+s] < rj[tid])) {
                    rv[tid] = rv[tid+s]; rj[tid] = rj[tid+s]; rs[tid] = rs[tid+s];
                }
            }
            __syncthreads();
        }
        if (tid == 0) { g_cand[row*NCAND + sel] = rj[0]; sv[rs[0]] = INF_F; }
        __syncthreads();
    }
}

// ---------------- kernel 2b: exact fp32 d2 for candidates -------------------
__global__ __launch_bounds__(256) void k_rerank(
    const float* __restrict__ Xt, const float* __restrict__ X)
{
    const int gw   = blockIdx.x * 8 + (threadIdx.x >> 5);  // 0..8191
    const int lane = threadIdx.x & 31;
    const int row  = gw >> 5;
    const int t    = gw & 31;
    const int j    = g_cand[row * NCAND + t];

    const float4* xa = (const float4*)(X  + (size_t)j   * DIM);
    const float4* xb = (const float4*)(Xt + (size_t)row * DIM);
    float s = 0.f;
#pragma unroll 4
    for (int i = lane; i < DIM / 4; i += 32) {
        const float4 a = xa[i], b = xb[i];
        s = fmaf(a.x, b.x, fmaf(a.y, b.y, fmaf(a.z, b.z, fmaf(a.w, b.w, s))));
    }
#pragma unroll
    for (int o = 16; o > 0; o >>= 1) s += __shfl_xor_sync(0xffffffffu, s, o);
    if (lane == 0) g_d2[row * NCAND + t] = g_ct[j] - 2.f * s;
}

// ---------------- kernel 2c: exact top-16 of the 32 candidates --------------
__global__ void k_sel16()
{
    const int row = blockIdx.x;
    const int t   = threadIdx.x;            // 32 threads
    const float myv = g_d2[row * NCAND + t];
    const int   myj = g_cand[row * NCAND + t];
    int rank = 0;
#pragma unroll
    for (int o = 0; o < NCAND; o++) {
        const float ov = __shfl_sync(0xffffffffu, myv, o);
        const int   oj = __shfl_sync(0xffffffffu, myj, o);
        rank += (ov < myv || (ov == myv && oj < myj)) ? 1 : 0;
    }
    if (rank < TOPK) g_topk[row * TOPK + rank] = myj;
}

// ---------------- kernel 3: exact L1 activation per (row, neighbor) ---------
__global__ __launch_bounds__(256) void k_l1(
    const float* __restrict__ Xt, const float* __restrict__ X,
    const float* __restrict__ w)
{
    const int gw   = blockIdx.x * 8 + (threadIdx.x >> 5);
    const int lane = threadIdx.x & 31;
    const int row  = gw >> 4;
    const int t    = gw & 15;
    const int j    = g_topk[row * TOPK + t];

    const float4* xa = (const float4*)(X  + (size_t)j   * DIM);
    const float4* xb = (const float4*)(Xt + (size_t)row * DIM);
    float s = 0.f;
#pragma unroll 4
    for (int i = lane; i < DIM / 4; i += 32) {
        const float4 a = xa[i], b = xb[i];
        s += fabsf(a.x-b.x) + fabsf(a.y-b.y) + fabsf(a.z-b.z) + fabsf(a.w-b.w);
    }
#pragma unroll
    for (int o = 16; o > 0; o >>= 1) s += __shfl_xor_sync(0xffffffffu, s, o);
    if (lane == 0) g_act[row * TOPK + t] = w[j] - KCONST * s;
}

// ---------------- kernel 3b: max over 16 activations ------------------------
__global__ __launch_bounds__(256) void k_max(float* __restrict__ out)
{
    const int row = threadIdx.x;
    float best = -INF_F;
#pragma unroll
    for (int t = 0; t < TOPK; t++) best = fmaxf(best, g_act[row * TOPK + t]);
    out[row] = best;
}

// ---------------------------------------------------------------------------
extern "C" void kernel_launch(void* const* d_in, const int* in_sizes, int n_in,
                              void* d_out, int out_size)
{
    const float* Xt = (const float*)d_in[0];
    const float* X  = (const float*)d_in[1];
    const float* w  = (const float*)d_in[2];
    float* out = (float*)d_out;

    cudaFuncSetAttribute(k_score, cudaFuncAttributeMaxDynamicSharedMemorySize,
                         SMEM_TOTAL);

    k_wmax<<<1, 256>>>(w, N_X);
    k_cvt<<<(N_X + M_Q + 7) / 8, 256>>>(Xt, X, w);
    k_score<<<N_TILES, 256, SMEM_TOTAL>>>();
    k_topk<<<M_Q, 256>>>();
    k_rerank<<<(M_Q * NCAND) / 8, 256>>>(Xt, X);
    k_sel16<<<M_Q, 32>>>();
    k_l1<<<(M_Q * TOPK) / 8, 256>>>(Xt, X, w);
    k_max<<<1, 256>>>(out);
}

// round 7
// speedup vs baseline: 7.6202x; 1.2710x over previous
#include <cuda_runtime.h>
#include <cuda_fp16.h>
#include <cstdint>
#include <cstddef>

#define M_Q    256
#define N_X    50000
#define DIM    3072
#define KCONST 750.0f
#define TOPK   16
#define NCAND  32

#define TILE_N  128
#define N_TILES 391              // ceil(50000/128)
#define KC      64               // k-chunk in halves (=128B rows)
#define CHUNKS  48               // 3072/64
#define A_BYTES (256*128)        // 32 KB
#define B_BYTES (128*128)        // 16 KB
#define STAGE   (A_BYTES + B_BYTES)
#define SMEM_TOTAL (3*STAGE)     // 144 KB

#define SEG    782               // 64*782 = 50048 >= 50000
#define NSEG   64

#define INF_F __int_as_float(0x7f800000)

// ---------------- device scratch ----------------
__device__ float  g_wmax;
__device__ __half g_Xh[(size_t)N_X * DIM];    // f16 copy of X
__device__ __half g_Xth[M_Q * DIM];           // f16 copy of X_tilde
__device__ float  g_ct[N_X];                  // exact |X_j|^2 + w'_j^2
__device__ float  g_scores[(size_t)M_Q * N_X];
__device__ unsigned long long g_cand1[M_Q * NSEG * 8];  // stage-1 candidates
__device__ int    g_cand[M_Q * NCAND];

// ---------------- helpers ----------------
__device__ __forceinline__ uint32_t h2_bits(__half2 h) {
    return *reinterpret_cast<uint32_t*>(&h);
}
__device__ __forceinline__ uint32_t smem_u32(const void* p) {
    uint32_t a;
    asm("{ .reg .u64 t; cvta.to.shared.u64 t, %1; cvt.u32.u64 %0, t; }" : "=r"(a) : "l"(p));
    return a;
}
__device__ __forceinline__ void cp16(uint32_t dst, const void* src, uint32_t sz) {
    asm volatile("cp.async.cg.shared.global [%0], [%1], 16, %2;"
                 :: "r"(dst), "l"(src), "r"(sz) : "memory");
}
#define CP_COMMIT() asm volatile("cp.async.commit_group;" ::: "memory")
#define CP_WAIT1()  asm volatile("cp.async.wait_group 1;" ::: "memory")

#define LDMATRIX_X4(r0, r1, r2, r3, addr)                                     \
    asm volatile("ldmatrix.sync.aligned.m8n8.x4.shared.b16 {%0,%1,%2,%3}, [%4];" \
                 : "=r"(r0), "=r"(r1), "=r"(r2), "=r"(r3) : "r"(addr))

#define MMA_F16(d, a, b)                                                       \
    asm volatile("mma.sync.aligned.m16n8k16.row.col.f32.f16.f16.f32 "          \
                 "{%0,%1,%2,%3}, {%4,%5,%6,%7}, {%8,%9}, {%0,%1,%2,%3};"       \
                 : "+f"((d)[0]), "+f"((d)[1]), "+f"((d)[2]), "+f"((d)[3])      \
                 : "r"((a)[0]), "r"((a)[1]), "r"((a)[2]), "r"((a)[3]),         \
                   "r"((b)[0]), "r"((b)[1]))

// ---------------- kernel 0: max(w) ----------------
__global__ __launch_bounds__(256) void k_wmax(const float* __restrict__ w, int n)
{
    __shared__ float sm[256];
    float v = -INF_F;
    for (int i = threadIdx.x; i < n; i += 256) v = fmaxf(v, w[i]);
    sm[threadIdx.x] = v;
    __syncthreads();
    for (int s = 128; s > 0; s >>= 1) {
        if (threadIdx.x < s) sm[threadIdx.x] = fmaxf(sm[threadIdx.x], sm[threadIdx.x + s]);
        __syncthreads();
    }
    if (threadIdx.x == 0) g_wmax = sm[0];
}

// ---------------- kernel 0b: fp32->f16 convert + exact col terms ------------
__global__ __launch_bounds__(256) void k_cvt(
    const float* __restrict__ Xt, const float* __restrict__ X,
    const float* __restrict__ w)
{
    const int warp = blockIdx.x * 8 + (threadIdx.x >> 5);
    const int lane = threadIdx.x & 31;
    if (warp >= N_X + M_Q) return;
    const bool isX = warp < N_X;
    const float4* src = (const float4*)(isX ? X + (size_t)warp * DIM
                                            : Xt + (size_t)(warp - N_X) * DIM);
    uint4* dst = (uint4*)(isX ? g_Xh + (size_t)warp * DIM
                              : g_Xth + (size_t)(warp - N_X) * DIM);
    float bsq = 0.f;
#pragma unroll 4
    for (int i = lane; i < DIM / 8; i += 32) {     // 12 iterations
        const float4 v0 = src[2*i], v1 = src[2*i + 1];
        bsq = fmaf(v0.x, v0.x, fmaf(v0.y, v0.y, fmaf(v0.z, v0.z, fmaf(v0.w, v0.w, bsq))));
        bsq = fmaf(v1.x, v1.x, fmaf(v1.y, v1.y, fmaf(v1.z, v1.z, fmaf(v1.w, v1.w, bsq))));
        uint4 o;
        o.x = h2_bits(__floats2half2_rn(v0.x, v0.y));
        o.y = h2_bits(__floats2half2_rn(v0.z, v0.w));
        o.z = h2_bits(__floats2half2_rn(v1.x, v1.y));
        o.w = h2_bits(__floats2half2_rn(v1.z, v1.w));
        dst[i] = o;
    }
    if (isX) {
#pragma unroll
        for (int o = 16; o > 0; o >>= 1) bsq += __shfl_xor_sync(0xffffffffu, bsq, o);
        if (lane == 0) {
            const float wp = (g_wmax - w[warp]) * (1.f / KCONST);
            g_ct[warp] = bsq + wp * wp;
        }
    }
}

// ---------------- kernel 1: f16 mma.sync scoring GEMM ----------------
__device__ __forceinline__ void issue_chunk_h(uint32_t sb, int buf, int c,
                                              int n0, int tid)
{
    const int k0 = c * KC;
    const uint32_t ab = sb + buf * STAGE;
    const uint32_t bb = ab + A_BYTES;
#pragma unroll
    for (int i = 0; i < 8; i++) {
        const int uid = tid + 256 * i;
        const int row = uid >> 3, u = uid & 7;
        cp16(ab + row * 128 + (((u) ^ (row & 7)) << 4),
             g_Xth + (size_t)row * DIM + k0 + u * 8, 16u);
    }
#pragma unroll
    for (int i = 0; i < 4; i++) {
        const int uid = tid + 256 * i;
        const int row = uid >> 3, u = uid & 7;
        const int gj  = n0 + row;
        const int gjc = gj < N_X ? gj : (N_X - 1);
        cp16(bb + row * 128 + (((u) ^ (row & 7)) << 4),
             g_Xh + (size_t)gjc * DIM + k0 + u * 8, gj < N_X ? 16u : 0u);
    }
}

__global__ __launch_bounds__(256, 1) void k_score()
{
    extern __shared__ char smem[];
    const uint32_t sb = smem_u32(smem);
    const int tid  = threadIdx.x;
    const int wid  = tid >> 5;
    const int lane = tid & 31;
    const int qr   = lane >> 2;
    const int qc   = lane & 3;
    const int wm   = wid >> 1;
    const int wn   = wid & 1;
    const int n0   = blockIdx.x * TILE_N;

    const int sel = lane >> 3;
    const int rl  = lane & 7;
    const int rA  = ((sel & 1) << 3) + rl;
    const int uA  = sel >> 1;
    const int rB  = ((sel >> 1) << 3) + rl;
    const int uB  = sel & 1;

    issue_chunk_h(sb, 0, 0, n0, tid); CP_COMMIT();
    issue_chunk_h(sb, 1, 1, n0, tid); CP_COMMIT();

    float acc[4][8][4];
#pragma unroll
    for (int mt = 0; mt < 4; mt++)
#pragma unroll
        for (int nt = 0; nt < 8; nt++)
#pragma unroll
            for (int q = 0; q < 4; q++) acc[mt][nt][q] = 0.f;

    for (int c = 0; c < CHUNKS; c++) {
        CP_WAIT1();
        __syncthreads();
        if (c + 2 < CHUNKS) issue_chunk_h(sb, (c + 2) % 3, c + 2, n0, tid);
        CP_COMMIT();

        const uint32_t Ab = sb + (c % 3) * STAGE;
        const uint32_t Bb = Ab + A_BYTES;

#pragma unroll
        for (int ks = 0; ks < 4; ks++) {
            uint32_t a[4][4], b[8][2];
#pragma unroll
            for (int mt = 0; mt < 4; mt++) {
                const int row = wm * 64 + mt * 16 + rA;
                const uint32_t addr = Ab + row * 128 + (((ks*2 + uA) ^ rl) << 4);
                LDMATRIX_X4(a[mt][0], a[mt][1], a[mt][2], a[mt][3], addr);
            }
#pragma unroll
            for (int p = 0; p < 4; p++) {
                const int row = wn * 64 + p * 16 + rB;
                const uint32_t addr = Bb + row * 128 + (((ks*2 + uB) ^ rl) << 4);
                LDMATRIX_X4(b[2*p][0], b[2*p][1], b[2*p+1][0], b[2*p+1][1], addr);
            }
#pragma unroll
            for (int mt = 0; mt < 4; mt++)
#pragma unroll
                for (int nt = 0; nt < 8; nt++)
                    MMA_F16(acc[mt][nt], a[mt], b[nt]);
        }
    }

    __syncthreads();
    float* cts = (float*)smem;
    if (tid < TILE_N) {
        const int j = n0 + tid;
        cts[tid] = (j < N_X) ? g_ct[j] : INF_F;
    }
    __syncthreads();

#pragma unroll
    for (int mt = 0; mt < 4; mt++) {
        const int r0 = wm * 64 + mt * 16 + qr;
#pragma unroll
        for (int nt = 0; nt < 8; nt++) {
            const int col = wn * 64 + nt * 8 + 2 * qc;
            const int j   = n0 + col;
            if (j < N_X) {
                const float c0 = cts[col], c1 = cts[col + 1];
                float2 v0 = { c0 - 2.f * acc[mt][nt][0], c1 - 2.f * acc[mt][nt][1] };
                float2 v1 = { c0 - 2.f * acc[mt][nt][2], c1 - 2.f * acc[mt][nt][3] };
                *(float2*)&g_scores[(size_t)r0 * N_X + j]       = v0;
                *(float2*)&g_scores[(size_t)(r0 + 8) * N_X + j] = v1;
            }
        }
    }
}

// ---------------- kernel 2a: stage-1 selection, warp top-8 per segment ------
// Packed key = (score_bits << 32) | idx. Scores positive -> bit order = value
// order; idx packing reproduces the lower-index tie-break exactly.
__global__ __launch_bounds__(256) void k_top1()
{
    const int gw   = blockIdx.x * 8 + (threadIdx.x >> 5);  // 0..16383
    const int lane = threadIdx.x & 31;
    const int row  = gw >> 6;
    const int ws   = gw & 63;
    const float* srow = g_scores + (size_t)row * N_X;
    const int base = ws * SEG;
    const int end  = (base + SEG < N_X) ? base + SEG : N_X;

    unsigned long long k0 = ~0ull, k1 = ~0ull, k2 = ~0ull, k3 = ~0ull;
    for (int i = base + lane; i < end; i += 32) {
        const unsigned long long k =
            ((unsigned long long)__float_as_uint(srow[i]) << 32) | (unsigned)i;
        if (k < k3) {
            if (k < k2) {
                k3 = k2;
                if (k < k1) { k2 = k1; if (k < k0) { k1 = k0; k0 = k; } else k1 = k; }
                else k2 = k;
            } else k3 = k;
        }
    }

    unsigned long long mine = ~0ull;
#pragma unroll
    for (int r = 0; r < 8; r++) {
        unsigned long long k = k0;
#pragma unroll
        for (int o = 16; o > 0; o >>= 1) {
            const unsigned long long t = __shfl_xor_sync(0xffffffffu, k, o);
            if (t < k) k = t;
        }
        if (lane == r) mine = k;
        if (k == k0) { k0 = k1; k1 = k2; k2 = k3; k3 = ~0ull; }
    }
    if (lane < 8) g_cand1[(row * NSEG + ws) * 8 + lane] = mine;
}

// ---------------- kernel 2b: stage-2, rank-select top-32 of 512 -------------
__global__ __launch_bounds__(256) void k_top2()
{
    __shared__ unsigned long long c[512];
    const int row = blockIdx.x, tid = threadIdx.x;
    c[tid]       = g_cand1[row * 512 + tid];
    c[tid + 256] = g_cand1[row * 512 + tid + 256];
    __syncthreads();

    const unsigned long long v0 = c[tid], v1 = c[tid + 256];
    int r0 = 0, r1 = 0;
    for (int o = 0; o < 512; o++) {
        const unsigned long long x = c[o];
        r0 += (x < v0);
        r1 += (x < v1);
    }
    if (r0 < NCAND) g_cand[row * NCAND + r0] = (int)(unsigned)(v0 & 0xffffffffu);
    if (r1 < NCAND) g_cand[row * NCAND + r1] = (int)(unsigned)(v1 & 0xffffffffu);
}

// ---------------- kernel 3: fused exact rerank + L1 + max -------------------
__global__ __launch_bounds__(256) void k_post(
    const float* __restrict__ Xt, const float* __restrict__ X,
    const float* __restrict__ w, float* __restrict__ out)
{
    __shared__ float xts[DIM];          // 12 KB query row
    __shared__ float d2s[NCAND];
    __shared__ float acts[NCAND];
    __shared__ int   idxs[NCAND];

    const int row  = blockIdx.x;
    const int tid  = threadIdx.x;
    const int warp = tid >> 5;
    const int lane = tid & 31;

    const float4* xtg = (const float4*)(Xt + (size_t)row * DIM);
    for (int i = tid; i < DIM / 4; i += 256) ((float4*)xts)[i] = xtg[i];
    __syncthreads();

    for (int t = warp; t < NCAND; t += 8) {
        const int j = g_cand[row * NCAND + t];
        const float4* xj  = (const float4*)(X + (size_t)j * DIM);
        const float4* xt4 = (const float4*)xts;
        float dot = 0.f, l1 = 0.f;
#pragma unroll 4
        for (int i = lane; i < DIM / 4; i += 32) {
            const float4 a = xj[i], b = xt4[i];
            dot = fmaf(a.x, b.x, fmaf(a.y, b.y, fmaf(a.z, b.z, fmaf(a.w, b.w, dot))));
            l1 += fabsf(a.x-b.x) + fabsf(a.y-b.y) + fabsf(a.z-b.z) + fabsf(a.w-b.w);
        }
#pragma unroll
        for (int o = 16; o > 0; o >>= 1) {
            dot += __shfl_xor_sync(0xffffffffu, dot, o);
            l1  += __shfl_xor_sync(0xffffffffu, l1,  o);
        }
        if (lane == 0) {
            d2s[t]  = g_ct[j] - 2.f * dot;
            acts[t] = w[j] - KCONST * l1;
            idxs[t] = j;
        }
    }
    __syncthreads();

    if (tid < 32) {
        const float v = d2s[tid];
        const int   j = idxs[tid];
        int rank = 0;
#pragma unroll
        for (int o = 0; o < NCAND; o++) {
            const float ov = __shfl_sync(0xffffffffu, v, o);
            const int   oj = __shfl_sync(0xffffffffu, j, o);
            rank += (ov < v || (ov == v && oj < j)) ? 1 : 0;
        }
        float a = (rank < TOPK) ? acts[tid] : -INF_F;
#pragma unroll
        for (int o = 16; o > 0; o >>= 1) a = fmaxf(a, __shfl_xor_sync(0xffffffffu, a, o));
        if (tid == 0) out[row] = a;
    }
}

// ---------------------------------------------------------------------------
extern "C" void kernel_launch(void* const* d_in, const int* in_sizes, int n_in,
                              void* d_out, int out_size)
{
    const float* Xt = (const float*)d_in[0];
    const float* X  = (const float*)d_in[1];
    const float* w  = (const float*)d_in[2];
    float* out = (float*)d_out;

    cudaFuncSetAttribute(k_score, cudaFuncAttributeMaxDynamicSharedMemorySize,
                         SMEM_TOTAL);

    k_wmax<<<1, 256>>>(w, N_X);
    k_cvt<<<(N_X + M_Q + 7) / 8, 256>>>(Xt, X, w);
    k_score<<<N_TILES, 256, SMEM_TOTAL>>>();
    k_top1<<<(M_Q * NSEG) / 8, 256>>>();
    k_top2<<<M_Q, 256>>>();
    k_post<<<M_Q, 256>>>(Xt, X, w, out);
}

// round 8
// speedup vs baseline: 8.0002x; 1.0499x over previous
#include <cuda_runtime.h>
#include <cuda_fp16.h>
#include <cstdint>
#include <cstddef>

#define M_Q    256
#define N_X    50000
#define DIM    3072
#define KCONST 750.0f
#define TOPK   16
#define NCAND  32

#define TILE_N  128
#define N_TILES 391              // ceil(50000/128)
#define KC      64               // k-chunk (elements)
#define CHUNKS  48               // 3072/64
#define A_STAGE 32768            // 256 rows x 128 B (f16)
#define B_TILE  16384            // 128 rows x 128 B (f16)
#define OFF_B   (3*A_STAGE)                 // 98304
#define OFF_CT  (OFF_B + 2*B_TILE)          // 131072
#define OFF_BSQ (OFF_CT + 512)              // 131584
#define SMEM_TOTAL (OFF_BSQ + 1024)         // 132608

#define SEG    784               // 64*784 = 50176 >= 50000, 16B aligned
#define NSEG   64

#define INF_F __int_as_float(0x7f800000)

// ---------------- device scratch ----------------
__device__ float  g_wmax;
__device__ __half g_Xth[M_Q * DIM];           // f16 copy of X_tilde only
__device__ float  g_ct[N_X];                  // exact |X_j|^2 + w'_j^2
__device__ float  g_scores[(size_t)M_Q * N_X];
__device__ unsigned long long g_cand1[M_Q * NSEG * 8];
__device__ int    g_cand[M_Q * NCAND];

// ---------------- helpers ----------------
__device__ __forceinline__ uint32_t h2_bits(__half2 h) {
    return *reinterpret_cast<uint32_t*>(&h);
}
__device__ __forceinline__ uint32_t smem_u32(const void* p) {
    uint32_t a;
    asm("{ .reg .u64 t; cvta.to.shared.u64 t, %1; cvt.u32.u64 %0, t; }" : "=r"(a) : "l"(p));
    return a;
}
__device__ __forceinline__ void cp16(uint32_t dst, const void* src) {
    asm volatile("cp.async.cg.shared.global [%0], [%1], 16;"
                 :: "r"(dst), "l"(src) : "memory");
}
#define CP_COMMIT() asm volatile("cp.async.commit_group;" ::: "memory")
#define CP_WAIT1()  asm volatile("cp.async.wait_group 1;" ::: "memory")

#define LDMATRIX_X4(r0, r1, r2, r3, addr)                                     \
    asm volatile("ldmatrix.sync.aligned.m8n8.x4.shared.b16 {%0,%1,%2,%3}, [%4];" \
                 : "=r"(r0), "=r"(r1), "=r"(r2), "=r"(r3) : "r"(addr))

#define MMA_F16(d, a, b)                                                       \
    asm volatile("mma.sync.aligned.m16n8k16.row.col.f32.f16.f16.f32 "          \
                 "{%0,%1,%2,%3}, {%4,%5,%6,%7}, {%8,%9}, {%0,%1,%2,%3};"       \
                 : "+f"((d)[0]), "+f"((d)[1]), "+f"((d)[2]), "+f"((d)[3])      \
                 : "r"((a)[0]), "r"((a)[1]), "r"((a)[2]), "r"((a)[3]),         \
                   "r"((b)[0]), "r"((b)[1]))

// ---------------- kernel 0: max(w) ----------------
__global__ __launch_bounds__(256) void k_wmax(const float* __restrict__ w, int n)
{
    __shared__ float sm[256];
    float v = -INF_F;
    for (int i = threadIdx.x; i < n; i += 256) v = fmaxf(v, w[i]);
    sm[threadIdx.x] = v;
    __syncthreads();
    for (int s = 128; s > 0; s >>= 1) {
        if (threadIdx.x < s) sm[threadIdx.x] = fmaxf(sm[threadIdx.x], sm[threadIdx.x + s]);
        __syncthreads();
    }
    if (threadIdx.x == 0) g_wmax = sm[0];
}

// ---------------- kernel 0b: convert X_tilde only (3 MB, ~3us) -------------
__global__ __launch_bounds__(256) void k_cvtA(const float* __restrict__ Xt)
{
    const int warp = blockIdx.x * 8 + (threadIdx.x >> 5);   // 0..255
    const int lane = threadIdx.x & 31;
    const float4* src = (const float4*)(Xt + (size_t)warp * DIM);
    uint4* dst = (uint4*)(g_Xth + (size_t)warp * DIM);
#pragma unroll 4
    for (int i = lane; i < DIM / 8; i += 32) {
        const float4 v0 = src[2*i], v1 = src[2*i + 1];
        uint4 o;
        o.x = h2_bits(__floats2half2_rn(v0.x, v0.y));
        o.y = h2_bits(__floats2half2_rn(v0.z, v0.w));
        o.z = h2_bits(__floats2half2_rn(v1.x, v1.y));
        o.w = h2_bits(__floats2half2_rn(v1.z, v1.w));
        dst[i] = o;
    }
}

// ---------------- kernel 1: fused f16 GEMM + inline X conversion -----------
// B (X columns) loaded fp32 via LDG -> cvt in regs -> STS f16 tile; |X_j|^2
// accumulated from the same registers. A (Xt f16) via 3-stage cp.async.
__device__ __forceinline__ void issueA(uint32_t sb, int buf, int c, int tid)
{
    const int k0 = c * KC;
    const uint32_t ab = sb + buf * A_STAGE;
#pragma unroll
    for (int i = 0; i < 8; i++) {
        const int uid = tid + 256 * i;
        const int row = uid >> 3, u = uid & 7;
        cp16(ab + row * 128 + ((u ^ (row & 7)) << 4),
             g_Xth + (size_t)row * DIM + k0 + u * 8);
    }
}

__global__ __launch_bounds__(256, 1) void k_score(
    const float* __restrict__ X, const float* __restrict__ w)
{
    extern __shared__ char smem[];
    const uint32_t sb = smem_u32(smem);
    const int tid  = threadIdx.x;
    const int wid  = tid >> 5;
    const int lane = tid & 31;
    const int qr   = lane >> 2;
    const int qc   = lane & 3;
    const int wm   = wid >> 1;
    const int wn   = wid & 1;
    const int n0   = blockIdx.x * TILE_N;

    // B producer mapping: thread -> (row, half-row of 32 floats)
    const int brow  = tid >> 1;
    const int bhalf = tid & 1;
    const int gj    = n0 + brow;
    const float4* bsrc = (const float4*)(X +
        (size_t)(gj < N_X ? gj : N_X - 1) * DIM + bhalf * 32);
    // STS addresses within a B tile (4x STS.128, XOR-16B swizzle)
    uint32_t sts_off[4];
#pragma unroll
    for (int q = 0; q < 4; q++)
        sts_off[q] = brow * 128 + (((bhalf * 4 + q) ^ (brow & 7)) << 4);

    // ldmatrix lane-address components
    const int sel = lane >> 3;
    const int rl  = lane & 7;
    const int rA  = ((sel & 1) << 3) + rl;
    const int uA  = sel >> 1;
    const int rB  = ((sel >> 1) << 3) + rl;
    const int uB  = sel & 1;

    issueA(sb, 0, 0, tid); CP_COMMIT();
    issueA(sb, 1, 1, tid); CP_COMMIT();

    float4 breg[8];
#pragma unroll
    for (int q = 0; q < 8; q++) breg[q] = bsrc[q];      // chunk 0

    float acc[4][8][4];
#pragma unroll
    for (int mt = 0; mt < 4; mt++)
#pragma unroll
        for (int nt = 0; nt < 8; nt++)
#pragma unroll
            for (int q = 0; q < 4; q++) acc[mt][nt][q] = 0.f;
    float bsq = 0.f;

    for (int c = 0; c < CHUNKS; c++) {
        // convert + store B chunk c, accumulate |X_j|^2
        const uint32_t bb = sb + OFF_B + (c & 1) * B_TILE;
#pragma unroll
        for (int q = 0; q < 4; q++) {
            const float4 v0 = breg[2*q], v1 = breg[2*q + 1];
            bsq = fmaf(v0.x, v0.x, fmaf(v0.y, v0.y, fmaf(v0.z, v0.z, fmaf(v0.w, v0.w, bsq))));
            bsq = fmaf(v1.x, v1.x, fmaf(v1.y, v1.y, fmaf(v1.z, v1.z, fmaf(v1.w, v1.w, bsq))));
            uint4 o;
            o.x = h2_bits(__floats2half2_rn(v0.x, v0.y));
            o.y = h2_bits(__floats2half2_rn(v0.z, v0.w));
            o.z = h2_bits(__floats2half2_rn(v1.x, v1.y));
            o.w = h2_bits(__floats2half2_rn(v1.z, v1.w));
            *(uint4*)(smem + (bb - sb) + sts_off[q]) = o;
        }

        CP_WAIT1();            // A stage c resident (c+1 in flight)
        __syncthreads();       // B tile visible + A stage (c-1)%3 free
        if (c + 2 < CHUNKS) { issueA(sb, (c + 2) % 3, c + 2, tid); }
        CP_COMMIT();

        if (c + 1 < CHUNKS) {  // prefetch B chunk c+1 into registers
            const float4* p = bsrc + (c + 1) * 16;
#pragma unroll
            for (int q = 0; q < 8; q++) breg[q] = p[q];
        }

        const uint32_t Ab = sb + (c % 3) * A_STAGE;
        const uint32_t Bb = sb + OFF_B + (c & 1) * B_TILE;
#pragma unroll
        for (int ks = 0; ks < 4; ks++) {
            uint32_t a[4][4], b[8][2];
#pragma unroll
            for (int mt = 0; mt < 4; mt++) {
                const int row = wm * 64 + mt * 16 + rA;
                const uint32_t addr = Ab + row * 128 + (((ks*2 + uA) ^ rl) << 4);
                LDMATRIX_X4(a[mt][0], a[mt][1], a[mt][2], a[mt][3], addr);
            }
#pragma unroll
            for (int p = 0; p < 4; p++) {
                const int row = wn * 64 + p * 16 + rB;
                const uint32_t addr = Bb + row * 128 + (((ks*2 + uB) ^ rl) << 4);
                LDMATRIX_X4(b[2*p][0], b[2*p][1], b[2*p+1][0], b[2*p+1][1], addr);
            }
#pragma unroll
            for (int mt = 0; mt < 4; mt++)
#pragma unroll
                for (int nt = 0; nt < 8; nt++)
                    MMA_F16(acc[mt][nt], a[mt], b[nt]);
        }
        __syncthreads();       // B tile (c&1) fully consumed before rewrite
    }

    // finish column terms: ct[j] = |X_j|^2 + w'_j^2 (exact fp32)
    float* bsqs = (float*)(smem + OFF_BSQ);
    float* cts  = (float*)(smem + OFF_CT);
    bsqs[tid] = bsq;
    __syncthreads();
    if (tid < TILE_N) {
        const int j = n0 + tid;
        float v = INF_F;
        if (j < N_X) {
            const float wp = (g_wmax - w[j]) * (1.f / KCONST);
            v = bsqs[2*tid] + bsqs[2*tid + 1] + wp * wp;
            g_ct[j] = v;
        }
        cts[tid] = v;
    }
    __syncthreads();

#pragma unroll
    for (int mt = 0; mt < 4; mt++) {
        const int r0 = wm * 64 + mt * 16 + qr;
#pragma unroll
        for (int nt = 0; nt < 8; nt++) {
            const int col = wn * 64 + nt * 8 + 2 * qc;
            const int j   = n0 + col;
            if (j < N_X) {
                const float c0 = cts[col], c1 = cts[col + 1];
                float2 v0 = { c0 - 2.f * acc[mt][nt][0], c1 - 2.f * acc[mt][nt][1] };
                float2 v1 = { c0 - 2.f * acc[mt][nt][2], c1 - 2.f * acc[mt][nt][3] };
                *(float2*)&g_scores[(size_t)r0 * N_X + j]       = v0;
                *(float2*)&g_scores[(size_t)(r0 + 8) * N_X + j] = v1;
            }
        }
    }
}

// ---------------- kernel 2a: stage-1 selection (uint keys, vec loads) ------
__global__ __launch_bounds__(256) void k_top1()
{
    const int gw   = blockIdx.x * 8 + (threadIdx.x >> 5);  // 0..16383
    const int lane = threadIdx.x & 31;
    const int row  = gw >> 6;
    const int ws   = gw & 63;
    const uint32_t* srow = (const uint32_t*)(g_scores + (size_t)row * N_X);
    const int base = ws * SEG;
    const int end  = (base + SEG < N_X) ? base + SEG : N_X;   // multiple of 4

    uint32_t bv0 = ~0u, bv1 = ~0u, bv2 = ~0u, bv3 = ~0u;
    int      bi0 = 0,   bi1 = 0,   bi2 = 0,   bi3 = 0;

#define INS(v, i) do {                                                         \
    if ((v) < bv3) {                                                           \
        if ((v) < bv2) {                                                       \
            bv3 = bv2; bi3 = bi2;                                              \
            if ((v) < bv1) {                                                   \
                bv2 = bv1; bi2 = bi1;                                          \
                if ((v) < bv0) { bv1 = bv0; bi1 = bi0; bv0 = (v); bi0 = (i); } \
                else           { bv1 = (v); bi1 = (i); }                       \
            } else { bv2 = (v); bi2 = (i); }                                   \
        } else { bv3 = (v); bi3 = (i); }                                       \
    }                                                                          \
} while (0)

    for (int i = base + lane * 4; i < end; i += 128) {
        const uint4 u = *(const uint4*)(srow + i);
        INS(u.x, i);
        INS(u.y, i + 1);
        INS(u.z, i + 2);
        INS(u.w, i + 3);
    }
#undef INS

    unsigned long long k0 = ((unsigned long long)bv0 << 32) | (unsigned)bi0;
    unsigned long long k1 = ((unsigned long long)bv1 << 32) | (unsigned)bi1;
    unsigned long long k2 = ((unsigned long long)bv2 << 32) | (unsigned)bi2;
    unsigned long long k3 = ((unsigned long long)bv3 << 32) | (unsigned)bi3;

    unsigned long long mine = ~0ull;
#pragma unroll
    for (int r = 0; r < 8; r++) {
        unsigned long long k = k0;
#pragma unroll
        for (int o = 16; o > 0; o >>= 1) {
            const unsigned long long t = __shfl_xor_sync(0xffffffffu, k, o);
            if (t < k) k = t;
        }
        if (lane == r) mine = k;
        if (k == k0) { k0 = k1; k1 = k2; k2 = k3; k3 = ~0ull; }
    }
    if (lane < 8) g_cand1[(row * NSEG + ws) * 8 + lane] = mine;
}

// ---------------- kernel 2b: stage-2, rank-select top-32 of 512 -------------
__global__ __launch_bounds__(256) void k_top2()
{
    __shared__ unsigned long long c[512];
    const int row = blockIdx.x, tid = threadIdx.x;
    c[tid]       = g_cand1[row * 512 + tid];
    c[tid + 256] = g_cand1[row * 512 + tid + 256];
    __syncthreads();

    const unsigned long long v0 = c[tid], v1 = c[tid + 256];
    int r0 = 0, r1 = 0;
    for (int o = 0; o < 512; o++) {
        const unsigned long long x = c[o];
        r0 += (x < v0);
        r1 += (x < v1);
    }
    if (r0 < NCAND) g_cand[row * NCAND + r0] = (int)(unsigned)(v0 & 0xffffffffu);
    if (r1 < NCAND) g_cand[row * NCAND + r1] = (int)(unsigned)(v1 & 0xffffffffu);
}

// ---------------- kernel 3: fused exact rerank + L1 + max -------------------
__global__ __launch_bounds__(256) void k_post(
    const float* __restrict__ Xt, const float* __restrict__ X,
    const float* __restrict__ w, float* __restrict__ out)
{
    __shared__ float xts[DIM];
    __shared__ float d2s[NCAND];
    __shared__ float acts[NCAND];
    __shared__ int   idxs[NCAND];

    const int row  = blockIdx.x;
    const int tid  = threadIdx.x;
    const int warp = tid >> 5;
    const int lane = tid & 31;

    const float4* xtg = (const float4*)(Xt + (size_t)row * DIM);
    for (int i = tid; i < DIM / 4; i += 256) ((float4*)xts)[i] = xtg[i];
    __syncthreads();

    for (int t = warp; t < NCAND; t += 8) {
        const int j = g_cand[row * NCAND + t];
        const float4* xj  = (const float4*)(X + (size_t)j * DIM);
        const float4* xt4 = (const float4*)xts;
        float dot = 0.f, l1 = 0.f;
#pragma unroll 4
        for (int i = lane; i < DIM / 4; i += 32) {
            const float4 a = xj[i], b = xt4[i];
            dot = fmaf(a.x, b.x, fmaf(a.y, b.y, fmaf(a.z, b.z, fmaf(a.w, b.w, dot))));
            l1 += fabsf(a.x-b.x) + fabsf(a.y-b.y) + fabsf(a.z-b.z) + fabsf(a.w-b.w);
        }
#pragma unroll
        for (int o = 16; o > 0; o >>= 1) {
            dot += __shfl_xor_sync(0xffffffffu, dot, o);
            l1  += __shfl_xor_sync(0xffffffffu, l1,  o);
        }
        if (lane == 0) {
            d2s[t]  = g_ct[j] - 2.f * dot;
            acts[t] = w[j] - KCONST * l1;
            idxs[t] = j;
        }
    }
    __syncthreads();

    if (tid < 32) {
        const float v = d2s[tid];
        const int   j = idxs[tid];
        int rank = 0;
#pragma unroll
        for (int o = 0; o < NCAND; o++) {
            const float ov = __shfl_sync(0xffffffffu, v, o);
            const int   oj = __shfl_sync(0xffffffffu, j, o);
            rank += (ov < v || (ov == v && oj < j)) ? 1 : 0;
        }
        float a = (rank < TOPK) ? acts[tid] : -INF_F;
#pragma unroll
        for (int o = 16; o > 0; o >>= 1) a = fmaxf(a, __shfl_xor_sync(0xffffffffu, a, o));
        if (tid == 0) out[row] = a;
    }
}

// ---------------------------------------------------------------------------
extern "C" void kernel_launch(void* const* d_in, const int* in_sizes, int n_in,
                              void* d_out, int out_size)
{
    const float* Xt = (const float*)d_in[0];
    const float* X  = (const float*)d_in[1];
    const float* w  = (const float*)d_in[2];
    float* out = (float*)d_out;

    cudaFuncSetAttribute(k_score, cudaFuncAttributeMaxDynamicSharedMemorySize,
                         SMEM_TOTAL);

    k_wmax<<<1, 256>>>(w, N_X);
    k_cvtA<<<32, 256>>>(Xt);
    k_score<<<N_TILES, 256, SMEM_TOTAL>>>(X, w);
    k_top1<<<(M_Q * NSEG) / 8, 256>>>();
    k_top2<<<M_Q, 256>>>();
    k_post<<<M_Q, 256>>>(Xt, X, w, out);
}

// round 9
// speedup vs baseline: 9.2520x; 1.1565x over previous
#include <cuda_runtime.h>
#include <cuda_fp16.h>
#include <cstdint>
#include <cstddef>

#define M_Q    256
#define N_X    50000
#define DIM    3072
#define KCONST 750.0f
#define TOPK   16
#define NCAND  32

#define TILE_N  128
#define N_TILES 391              // ceil(50000/128)
#define KC      64               // k-chunk (elements)
#define CHUNKS  48               // 3072/64
#define A_STAGE   32768          // 256 rows x 128 B (f16)
#define BF32_STAGE 32768         // 128 rows x 256 B (fp32)
#define OFF_BF32 (3*A_STAGE)                 // 98304
#define OFF_BH   (OFF_BF32 + 3*BF32_STAGE)   // 196608 (f16 B tile, 16 KB)
#define OFF_CT   (OFF_BH + 16384)            // 212992
#define OFF_BSQ  (OFF_CT + 512)              // 213504
#define SMEM_TOTAL (OFF_BSQ + 1024)          // 214528

#define SEG    784               // 64*784 = 50176 >= 50000, 16B aligned
#define NSEG   64

#define INF_F __int_as_float(0x7f800000)

// ---------------- device scratch ----------------
__device__ float  g_wmax;
__device__ __half g_Xth[M_Q * DIM];           // f16 copy of X_tilde only
__device__ float  g_ct[N_X];                  // exact |X_j|^2 + w'_j^2
__device__ float  g_scores[(size_t)M_Q * N_X];
__device__ unsigned long long g_cand1[M_Q * NSEG * 8];
__device__ int    g_cand[M_Q * NCAND];

// ---------------- helpers ----------------
__device__ __forceinline__ uint32_t h2_bits(__half2 h) {
    return *reinterpret_cast<uint32_t*>(&h);
}
__device__ __forceinline__ uint32_t smem_u32(const void* p) {
    uint32_t a;
    asm("{ .reg .u64 t; cvta.to.shared.u64 t, %1; cvt.u32.u64 %0, t; }" : "=r"(a) : "l"(p));
    return a;
}
__device__ __forceinline__ void cp16(uint32_t dst, const void* src) {
    asm volatile("cp.async.cg.shared.global [%0], [%1], 16;"
                 :: "r"(dst), "l"(src) : "memory");
}
#define CP_COMMIT() asm volatile("cp.async.commit_group;" ::: "memory")
#define CP_WAIT1()  asm volatile("cp.async.wait_group 1;" ::: "memory")

#define LDMATRIX_X4(r0, r1, r2, r3, addr)                                     \
    asm volatile("ldmatrix.sync.aligned.m8n8.x4.shared.b16 {%0,%1,%2,%3}, [%4];" \
                 : "=r"(r0), "=r"(r1), "=r"(r2), "=r"(r3) : "r"(addr))

#define MMA_F16(d, a, b)                                                       \
    asm volatile("mma.sync.aligned.m16n8k16.row.col.f32.f16.f16.f32 "          \
                 "{%0,%1,%2,%3}, {%4,%5,%6,%7}, {%8,%9}, {%0,%1,%2,%3};"       \
                 : "+f"((d)[0]), "+f"((d)[1]), "+f"((d)[2]), "+f"((d)[3])      \
                 : "r"((a)[0]), "r"((a)[1]), "r"((a)[2]), "r"((a)[3]),         \
                   "r"((b)[0]), "r"((b)[1]))

// ---------------- kernel 0: max(w) ----------------
__global__ __launch_bounds__(256) void k_wmax(const float* __restrict__ w, int n)
{
    __shared__ float sm[256];
    float v = -INF_F;
    for (int i = threadIdx.x; i < n; i += 256) v = fmaxf(v, w[i]);
    sm[threadIdx.x] = v;
    __syncthreads();
    for (int s = 128; s > 0; s >>= 1) {
        if (threadIdx.x < s) sm[threadIdx.x] = fmaxf(sm[threadIdx.x], sm[threadIdx.x + s]);
        __syncthreads();
    }
    if (threadIdx.x == 0) g_wmax = sm[0];
}

// ---------------- kernel 0b: convert X_tilde only (3 MB) -------------------
__global__ __launch_bounds__(256) void k_cvtA(const float* __restrict__ Xt)
{
    const int warp = blockIdx.x * 8 + (threadIdx.x >> 5);   // 0..255
    const int lane = threadIdx.x & 31;
    const float4* src = (const float4*)(Xt + (size_t)warp * DIM);
    uint4* dst = (uint4*)(g_Xth + (size_t)warp * DIM);
#pragma unroll 4
    for (int i = lane; i < DIM / 8; i += 32) {
        const float4 v0 = src[2*i], v1 = src[2*i + 1];
        uint4 o;
        o.x = h2_bits(__floats2half2_rn(v0.x, v0.y));
        o.y = h2_bits(__floats2half2_rn(v0.z, v0.w));
        o.z = h2_bits(__floats2half2_rn(v1.x, v1.y));
        o.w = h2_bits(__floats2half2_rn(v1.z, v1.w));
        dst[i] = o;
    }
}

// ---------------- kernel 1: fused f16 GEMM, B converted via SMEM -----------
// A (Xt f16) and B (X fp32) both stream through 3-stage cp.async pipelines.
// Each chunk: smem fp32 -> registers -> f16 smem tile (+ |X_j|^2), then MMA.
__device__ __forceinline__ void issueAB(uint32_t sb, int stage, int c,
                                        const float* __restrict__ X,
                                        int n0, int tid)
{
    const int k0 = c * KC;
    const uint32_t ab = sb + stage * A_STAGE;
    const uint32_t bb = sb + OFF_BF32 + stage * BF32_STAGE;
#pragma unroll
    for (int i = 0; i < 8; i++) {                 // A: 2048 16B units (f16)
        const int uid = tid + 256 * i;
        const int row = uid >> 3, u = uid & 7;
        cp16(ab + row * 128 + ((u ^ (row & 7)) << 4),
             g_Xth + (size_t)row * DIM + k0 + u * 8);
    }
#pragma unroll
    for (int i = 0; i < 8; i++) {                 // B: 2048 16B units (fp32)
        const int uid = tid + 256 * i;
        const int row = uid >> 4, u = uid & 15;
        const int gj  = n0 + row;
        cp16(bb + row * 256 + ((u ^ (row & 15)) << 4),
             X + (size_t)(gj < N_X ? gj : N_X - 1) * DIM + k0 + u * 4);
    }
}

__global__ __launch_bounds__(256, 1) void k_score(
    const float* __restrict__ X, const float* __restrict__ w)
{
    extern __shared__ char smem[];
    const uint32_t sb = smem_u32(smem);
    const int tid  = threadIdx.x;
    const int wid  = tid >> 5;
    const int lane = tid & 31;
    const int qr   = lane >> 2;
    const int qc   = lane & 3;
    const int wm   = wid >> 1;
    const int wn   = wid & 1;
    const int n0   = blockIdx.x * TILE_N;

    // conversion mapping: thread -> (row, half of 32 floats)
    const int brow  = tid >> 1;
    const int bhalf = tid & 1;
    // fp32 source offsets (swizzled) and f16 dest offsets (swizzled)
    uint32_t ld_off[8], sts_off[4];
#pragma unroll
    for (int u = 0; u < 8; u++)
        ld_off[u] = brow * 256 + (((bhalf * 8 + u) ^ (brow & 15)) << 4);
#pragma unroll
    for (int q = 0; q < 4; q++)
        sts_off[q] = brow * 128 + (((bhalf * 4 + q) ^ (brow & 7)) << 4);

    // ldmatrix lane-address components
    const int sel = lane >> 3;
    const int rl  = lane & 7;
    const int rA  = ((sel & 1) << 3) + rl;
    const int uA  = sel >> 1;
    const int rB  = ((sel >> 1) << 3) + rl;
    const int uB  = sel & 1;

    issueAB(sb, 0, 0, X, n0, tid); CP_COMMIT();
    issueAB(sb, 1, 1, X, n0, tid); CP_COMMIT();

    float acc[4][8][4];
#pragma unroll
    for (int mt = 0; mt < 4; mt++)
#pragma unroll
        for (int nt = 0; nt < 8; nt++)
#pragma unroll
            for (int q = 0; q < 4; q++) acc[mt][nt][q] = 0.f;
    float bsq = 0.f;

    for (int c = 0; c < CHUNKS; c++) {
        CP_WAIT1();            // chunk c (A f16 + B fp32) resident
        __syncthreads();       // also: all warps done with stage (c-1)%3 reads

        // convert B fp32 -> f16 tile, accumulate |X_j|^2
        const char* bf = smem + OFF_BF32 + (c % 3) * BF32_STAGE;
        char* bh = smem + OFF_BH;
#pragma unroll
        for (int q = 0; q < 4; q++) {
            const float4 v0 = *(const float4*)(bf + ld_off[2*q]);
            const float4 v1 = *(const float4*)(bf + ld_off[2*q + 1]);
            bsq = fmaf(v0.x, v0.x, fmaf(v0.y, v0.y, fmaf(v0.z, v0.z, fmaf(v0.w, v0.w, bsq))));
            bsq = fmaf(v1.x, v1.x, fmaf(v1.y, v1.y, fmaf(v1.z, v1.z, fmaf(v1.w, v1.w, bsq))));
            uint4 o;
            o.x = h2_bits(__floats2half2_rn(v0.x, v0.y));
            o.y = h2_bits(__floats2half2_rn(v0.z, v0.w));
            o.z = h2_bits(__floats2half2_rn(v1.x, v1.y));
            o.w = h2_bits(__floats2half2_rn(v1.z, v1.w));
            *(uint4*)(bh + sts_off[q]) = o;
        }
        __syncthreads();       // f16 tile visible to all warps

        if (c + 2 < CHUNKS) issueAB(sb, (c + 2) % 3, c + 2, X, n0, tid);
        CP_COMMIT();

        const uint32_t Ab = sb + (c % 3) * A_STAGE;
        const uint32_t Bb = sb + OFF_BH;
#pragma unroll
        for (int ks = 0; ks < 4; ks++) {
            uint32_t a[4][4], b[8][2];
#pragma unroll
            for (int mt = 0; mt < 4; mt++) {
                const int row = wm * 64 + mt * 16 + rA;
                const uint32_t addr = Ab + row * 128 + (((ks*2 + uA) ^ rl) << 4);
                LDMATRIX_X4(a[mt][0], a[mt][1], a[mt][2], a[mt][3], addr);
            }
#pragma unroll
            for (int p = 0; p < 4; p++) {
                const int row = wn * 64 + p * 16 + rB;
                const uint32_t addr = Bb + row * 128 + (((ks*2 + uB) ^ rl) << 4);
                LDMATRIX_X4(b[2*p][0], b[2*p][1], b[2*p+1][0], b[2*p+1][1], addr);
            }
#pragma unroll
            for (int mt = 0; mt < 4; mt++)
#pragma unroll
                for (int nt = 0; nt < 8; nt++)
                    MMA_F16(acc[mt][nt], a[mt], b[nt]);
        }
    }

    // finish column terms: ct[j] = |X_j|^2 + w'_j^2 (exact fp32)
    float* bsqs = (float*)(smem + OFF_BSQ);
    float* cts  = (float*)(smem + OFF_CT);
    __syncthreads();
    bsqs[tid] = bsq;
    __syncthreads();
    if (tid < TILE_N) {
        const int j = n0 + tid;
        float v = INF_F;
        if (j < N_X) {
            const float wp = (g_wmax - w[j]) * (1.f / KCONST);
            v = bsqs[2*tid] + bsqs[2*tid + 1] + wp * wp;
            g_ct[j] = v;
        }
        cts[tid] = v;
    }
    __syncthreads();

#pragma unroll
    for (int mt = 0; mt < 4; mt++) {
        const int r0 = wm * 64 + mt * 16 + qr;
#pragma unroll
        for (int nt = 0; nt < 8; nt++) {
            const int col = wn * 64 + nt * 8 + 2 * qc;
            const int j   = n0 + col;
            if (j < N_X) {
                const float c0 = cts[col], c1 = cts[col + 1];
                float2 v0 = { c0 - 2.f * acc[mt][nt][0], c1 - 2.f * acc[mt][nt][1] };
                float2 v1 = { c0 - 2.f * acc[mt][nt][2], c1 - 2.f * acc[mt][nt][3] };
                *(float2*)&g_scores[(size_t)r0 * N_X + j]       = v0;
                *(float2*)&g_scores[(size_t)(r0 + 8) * N_X + j] = v1;
            }
        }
    }
}

// ---------------- kernel 2a: stage-1 selection (uint keys, vec loads) ------
__global__ __launch_bounds__(256) void k_top1()
{
    const int gw   = blockIdx.x * 8 + (threadIdx.x >> 5);  // 0..16383
    const int lane = threadIdx.x & 31;
    const int row  = gw >> 6;
    const int ws   = gw & 63;
    const uint32_t* srow = (const uint32_t*)(g_scores + (size_t)row * N_X);
    const int base = ws * SEG;
    const int end  = (base + SEG < N_X) ? base + SEG : N_X;   // multiple of 4

    uint32_t bv0 = ~0u, bv1 = ~0u, bv2 = ~0u, bv3 = ~0u;
    int      bi0 = 0,   bi1 = 0,   bi2 = 0,   bi3 = 0;

#define INS(v, i) do {                                                         \
    if ((v) < bv3) {                                                           \
        if ((v) < bv2) {                                                       \
            bv3 = bv2; bi3 = bi2;                                              \
            if ((v) < bv1) {                                                   \
                bv2 = bv1; bi2 = bi1;                                          \
                if ((v) < bv0) { bv1 = bv0; bi1 = bi0; bv0 = (v); bi0 = (i); } \
                else           { bv1 = (v); bi1 = (i); }                       \
            } else { bv2 = (v); bi2 = (i); }                                   \
        } else { bv3 = (v); bi3 = (i); }                                       \
    }                                                                          \
} while (0)

    for (int i = base + lane * 4; i < end; i += 128) {
        const uint4 u = *(const uint4*)(srow + i);
        INS(u.x, i);
        INS(u.y, i + 1);
        INS(u.z, i + 2);
        INS(u.w, i + 3);
    }
#undef INS

    unsigned long long k0 = ((unsigned long long)bv0 << 32) | (unsigned)bi0;
    unsigned long long k1 = ((unsigned long long)bv1 << 32) | (unsigned)bi1;
    unsigned long long k2 = ((unsigned long long)bv2 << 32) | (unsigned)bi2;
    unsigned long long k3 = ((unsigned long long)bv3 << 32) | (unsigned)bi3;

    unsigned long long mine = ~0ull;
#pragma unroll
    for (int r = 0; r < 8; r++) {
        unsigned long long k = k0;
#pragma unroll
        for (int o = 16; o > 0; o >>= 1) {
            const unsigned long long t = __shfl_xor_sync(0xffffffffu, k, o);
            if (t < k) k = t;
        }
        if (lane == r) mine = k;
        if (k == k0) { k0 = k1; k1 = k2; k2 = k3; k3 = ~0ull; }
    }
    if (lane < 8) g_cand1[(row * NSEG + ws) * 8 + lane] = mine;
}

// ---------------- kernel 2b: stage-2, rank-select top-32 of 512 -------------
__global__ __launch_bounds__(256) void k_top2()
{
    __shared__ unsigned long long c[512];
    const int row = blockIdx.x, tid = threadIdx.x;
    c[tid]       = g_cand1[row * 512 + tid];
    c[tid + 256] = g_cand1[row * 512 + tid + 256];
    __syncthreads();

    const unsigned long long v0 = c[tid], v1 = c[tid + 256];
    int r0 = 0, r1 = 0;
    for (int o = 0; o < 512; o++) {
        const unsigned long long x = c[o];
        r0 += (x < v0);
        r1 += (x < v1);
    }
    if (r0 < NCAND) g_cand[row * NCAND + r0] = (int)(unsigned)(v0 & 0xffffffffu);
    if (r1 < NCAND) g_cand[row * NCAND + r1] = (int)(unsigned)(v1 & 0xffffffffu);
}

// ---------------- kernel 3: fused exact rerank + L1 + max -------------------
__global__ __launch_bounds__(256) void k_post(
    const float* __restrict__ Xt, const float* __restrict__ X,
    const float* __restrict__ w, float* __restrict__ out)
{
    __shared__ float xts[DIM];
    __shared__ float d2s[NCAND];
    __shared__ float acts[NCAND];
    __shared__ int   idxs[NCAND];

    const int row  = blockIdx.x;
    const int tid  = threadIdx.x;
    const int warp = tid >> 5;
    const int lane = tid & 31;

    const float4* xtg = (const float4*)(Xt + (size_t)row * DIM);
    for (int i = tid; i < DIM / 4; i += 256) ((float4*)xts)[i] = xtg[i];
    __syncthreads();

    for (int t = warp; t < NCAND; t += 8) {
        const int j = g_cand[row * NCAND + t];
        const float4* xj  = (const float4*)(X + (size_t)j * DIM);
        const float4* xt4 = (const float4*)xts;
        float dot = 0.f, l1 = 0.f;
#pragma unroll 4
        for (int i = lane; i < DIM / 4; i += 32) {
            const float4 a = xj[i], b = xt4[i];
            dot = fmaf(a.x, b.x, fmaf(a.y, b.y, fmaf(a.z, b.z, fmaf(a.w, b.w, dot))));
            l1 += fabsf(a.x-b.x) + fabsf(a.y-b.y) + fabsf(a.z-b.z) + fabsf(a.w-b.w);
        }
#pragma unroll
        for (int o = 16; o > 0; o >>= 1) {
            dot += __shfl_xor_sync(0xffffffffu, dot, o);
            l1  += __shfl_xor_sync(0xffffffffu, l1,  o);
        }
        if (lane == 0) {
            d2s[t]  = g_ct[j] - 2.f * dot;
            acts[t] = w[j] - KCONST * l1;
            idxs[t] = j;
        }
    }
    __syncthreads();

    if (tid < 32) {
        const float v = d2s[tid];
        const int   j = idxs[tid];
        int rank = 0;
#pragma unroll
        for (int o = 0; o < NCAND; o++) {
            const float ov = __shfl_sync(0xffffffffu, v, o);
            const int   oj = __shfl_sync(0xffffffffu, j, o);
            rank += (ov < v || (ov == v && oj < j)) ? 1 : 0;
        }
        float a = (rank < TOPK) ? acts[tid] : -INF_F;
#pragma unroll
        for (int o = 16; o > 0; o >>= 1) a = fmaxf(a, __shfl_xor_sync(0xffffffffu, a, o));
        if (tid == 0) out[row] = a;
    }
}

// ---------------------------------------------------------------------------
extern "C" void kernel_launch(void* const* d_in, const int* in_sizes, int n_in,
                              void* d_out, int out_size)
{
    const float* Xt = (const float*)d_in[0];
    const float* X  = (const float*)d_in[1];
    const float* w  = (const float*)d_in[2];
    float* out = (float*)d_out;

    cudaFuncSetAttribute(k_score, cudaFuncAttributeMaxDynamicSharedMemorySize,
                         SMEM_TOTAL);

    k_wmax<<<1, 256>>>(w, N_X);
    k_cvtA<<<32, 256>>>(Xt);
    k_score<<<N_TILES, 256, SMEM_TOTAL>>>(X, w);
    k_top1<<<(M_Q * NSEG) / 8, 256>>>();
    k_top2<<<M_Q, 256>>>();
    k_post<<<M_Q, 256>>>(Xt, X, w, out);
}

// round 10
// speedup vs baseline: 9.7246x; 1.0511x over previous
#include <cuda_runtime.h>
#include <cuda_fp16.h>
#include <cstdint>
#include <cstddef>

#define M_Q    256
#define N_X    50000
#define DIM    3072
#define KCONST 750.0f
#define TOPK   16
#define NCAND  32

#define TILE_N  128
#define N_TILES 391              // ceil(50000/128)
#define KC      64               // k-chunk (elements)
#define CHUNKS  48               // 3072/64
#define A_STAGE    32768         // 256 rows x 128 B (f16), x3
#define BF32_STAGE 32768         // 128 rows x 256 B (fp32), x2
#define OFF_BF32 (3*A_STAGE)                  // 98304
#define OFF_BH   (OFF_BF32 + 2*BF32_STAGE)    // 163840 (f16 B tile x2)
#define OFF_CT   (OFF_BH + 2*16384)           // 196608
#define OFF_BSQ  (OFF_CT + 512)               // 197120
#define SMEM_TOTAL (OFF_BSQ + 1024)           // 198144

#define SEG    784               // 64*784 = 50176 >= 50000, 16B aligned
#define NSEG   64

#define INF_F __int_as_float(0x7f800000)

// ---------------- device scratch ----------------
__device__ float  g_wmax;
__device__ __half g_Xth[M_Q * DIM];           // f16 copy of X_tilde only
__device__ float  g_ct[N_X];                  // exact |X_j|^2 + w'_j^2
__device__ float  g_scores[(size_t)M_Q * N_X];
__device__ unsigned long long g_cand1[M_Q * NSEG * 8];
__device__ int    g_cand[M_Q * NCAND];

// ---------------- helpers ----------------
__device__ __forceinline__ uint32_t h2_bits(__half2 h) {
    return *reinterpret_cast<uint32_t*>(&h);
}
__device__ __forceinline__ uint32_t smem_u32(const void* p) {
    uint32_t a;
    asm("{ .reg .u64 t; cvta.to.shared.u64 t, %1; cvt.u32.u64 %0, t; }" : "=r"(a) : "l"(p));
    return a;
}
__device__ __forceinline__ void cp16(uint32_t dst, const void* src) {
    asm volatile("cp.async.cg.shared.global [%0], [%1], 16;"
                 :: "r"(dst), "l"(src) : "memory");
}
#define CP_COMMIT() asm volatile("cp.async.commit_group;" ::: "memory")
#define CP_WAIT1()  asm volatile("cp.async.wait_group 1;" ::: "memory")
#define CP_WAIT0()  asm volatile("cp.async.wait_group 0;" ::: "memory")

#define LDMATRIX_X4(r0, r1, r2, r3, addr)                                     \
    asm volatile("ldmatrix.sync.aligned.m8n8.x4.shared.b16 {%0,%1,%2,%3}, [%4];" \
                 : "=r"(r0), "=r"(r1), "=r"(r2), "=r"(r3) : "r"(addr))

#define MMA_F16(d, a, b)                                                       \
    asm volatile("mma.sync.aligned.m16n8k16.row.col.f32.f16.f16.f32 "          \
                 "{%0,%1,%2,%3}, {%4,%5,%6,%7}, {%8,%9}, {%0,%1,%2,%3};"       \
                 : "+f"((d)[0]), "+f"((d)[1]), "+f"((d)[2]), "+f"((d)[3])      \
                 : "r"((a)[0]), "r"((a)[1]), "r"((a)[2]), "r"((a)[3]),         \
                   "r"((b)[0]), "r"((b)[1]))

// ---------------- kernel 0: max(w) ----------------
__global__ __launch_bounds__(256) void k_wmax(const float* __restrict__ w, int n)
{
    __shared__ float sm[256];
    float v = -INF_F;
    for (int i = threadIdx.x; i < n; i += 256) v = fmaxf(v, w[i]);
    sm[threadIdx.x] = v;
    __syncthreads();
    for (int s = 128; s > 0; s >>= 1) {
        if (threadIdx.x < s) sm[threadIdx.x] = fmaxf(sm[threadIdx.x], sm[threadIdx.x + s]);
        __syncthreads();
    }
    if (threadIdx.x == 0) g_wmax = sm[0];
}

// ---------------- kernel 0b: convert X_tilde only (3 MB) -------------------
__global__ __launch_bounds__(256) void k_cvtA(const float* __restrict__ Xt)
{
    const int warp = blockIdx.x * 8 + (threadIdx.x >> 5);   // 0..255
    const int lane = threadIdx.x & 31;
    const float4* src = (const float4*)(Xt + (size_t)warp * DIM);
    uint4* dst = (uint4*)(g_Xth + (size_t)warp * DIM);
#pragma unroll 4
    for (int i = lane; i < DIM / 8; i += 32) {
        const float4 v0 = src[2*i], v1 = src[2*i + 1];
        uint4 o;
        o.x = h2_bits(__floats2half2_rn(v0.x, v0.y));
        o.y = h2_bits(__floats2half2_rn(v0.z, v0.w));
        o.z = h2_bits(__floats2half2_rn(v1.x, v1.y));
        o.w = h2_bits(__floats2half2_rn(v1.z, v1.w));
        dst[i] = o;
    }
}

// ---------------- kernel 1: fused f16 GEMM, overlapped B conversion --------
// Iteration c: convert chunk c+1 (fp32 smem -> f16 BH[(c+1)&1]) issued BEFORE
// the MMA section of chunk c (reads BH[c&1]) -> conversion hides under MMA.
// One __syncthreads per chunk. A f16 x3 stages, B fp32 x2 stages, BH x2.
__device__ __forceinline__ void issueAB(uint32_t sb, int c,
                                        const float* __restrict__ X,
                                        int n0, int tid)
{
    const int k0 = c * KC;
    const uint32_t ab = sb + (c % 3) * A_STAGE;
    const uint32_t bb = sb + OFF_BF32 + (c & 1) * BF32_STAGE;
#pragma unroll
    for (int i = 0; i < 8; i++) {                 // A: 2048 16B units (f16)
        const int uid = tid + 256 * i;
        const int row = uid >> 3, u = uid & 7;
        cp16(ab + row * 128 + ((u ^ (row & 7)) << 4),
             g_Xth + (size_t)row * DIM + k0 + u * 8);
    }
#pragma unroll
    for (int i = 0; i < 8; i++) {                 // B: 2048 16B units (fp32)
        const int uid = tid + 256 * i;
        const int row = uid >> 4, u = uid & 15;
        const int gj  = n0 + row;
        cp16(bb + row * 256 + ((u ^ (row & 15)) << 4),
             X + (size_t)(gj < N_X ? gj : N_X - 1) * DIM + k0 + u * 4);
    }
}

__global__ __launch_bounds__(256, 1) void k_score(
    const float* __restrict__ X, const float* __restrict__ w)
{
    extern __shared__ char smem[];
    const uint32_t sb = smem_u32(smem);
    const int tid  = threadIdx.x;
    const int wid  = tid >> 5;
    const int lane = tid & 31;
    const int qr   = lane >> 2;
    const int qc   = lane & 3;
    const int wm   = wid >> 1;
    const int wn   = wid & 1;
    const int n0   = blockIdx.x * TILE_N;

    // conversion mapping: thread -> (row, half of 32 floats)
    const int brow  = tid >> 1;
    const int bhalf = tid & 1;
    uint32_t ld_off[8], sts_off[4];
#pragma unroll
    for (int u = 0; u < 8; u++)
        ld_off[u] = brow * 256 + (((bhalf * 8 + u) ^ (brow & 15)) << 4);
#pragma unroll
    for (int q = 0; q < 4; q++)
        sts_off[q] = brow * 128 + (((bhalf * 4 + q) ^ (brow & 7)) << 4);

    // ldmatrix lane-address components
    const int sel = lane >> 3;
    const int rl  = lane & 7;
    const int rA  = ((sel & 1) << 3) + rl;
    const int uA  = sel >> 1;
    const int rB  = ((sel >> 1) << 3) + rl;
    const int uB  = sel & 1;

    float bsq = 0.f;

    // conversion body: fp32 stage (cc&1) -> BH[cc&1], accumulate |X_j|^2
#define CONVERT(cc) do {                                                       \
        const char* bf = smem + OFF_BF32 + ((cc) & 1) * BF32_STAGE;            \
        char* bh = smem + OFF_BH + ((cc) & 1) * 16384;                         \
        _Pragma("unroll")                                                      \
        for (int q = 0; q < 4; q++) {                                          \
            const float4 v0 = *(const float4*)(bf + ld_off[2*q]);              \
            const float4 v1 = *(const float4*)(bf + ld_off[2*q + 1]);          \
            bsq = fmaf(v0.x, v0.x, fmaf(v0.y, v0.y,                            \
                  fmaf(v0.z, v0.z, fmaf(v0.w, v0.w, bsq))));                   \
            bsq = fmaf(v1.x, v1.x, fmaf(v1.y, v1.y,                            \
                  fmaf(v1.z, v1.z, fmaf(v1.w, v1.w, bsq))));                   \
            uint4 o;                                                           \
            o.x = h2_bits(__floats2half2_rn(v0.x, v0.y));                      \
            o.y = h2_bits(__floats2half2_rn(v0.z, v0.w));                      \
            o.z = h2_bits(__floats2half2_rn(v1.x, v1.y));                      \
            o.w = h2_bits(__floats2half2_rn(v1.z, v1.w));                      \
            *(uint4*)(bh + sts_off[q]) = o;                                    \
        }                                                                      \
    } while (0)

    // prologue: chunks 0 and 1 in flight; convert chunk 0
    issueAB(sb, 0, X, n0, tid); CP_COMMIT();
    issueAB(sb, 1, X, n0, tid); CP_COMMIT();
    CP_WAIT1();
    __syncthreads();
    CONVERT(0);

    float acc[4][8][4];
#pragma unroll
    for (int mt = 0; mt < 4; mt++)
#pragma unroll
        for (int nt = 0; nt < 8; nt++)
#pragma unroll
            for (int q = 0; q < 4; q++) acc[mt][nt][q] = 0.f;

    for (int c = 0; c < CHUNKS; c++) {
        CP_WAIT0();            // chunk c+1 fp32+f16A resident (if any pending)
        __syncthreads();       // MMA(c-1) done; convert(c) visible everywhere

        if (c + 1 < CHUNKS) CONVERT(c + 1);          // overlaps with MMA(c)
        if (c + 2 < CHUNKS) { issueAB(sb, c + 2, X, n0, tid); CP_COMMIT(); }

        const uint32_t Ab = sb + (c % 3) * A_STAGE;
        const uint32_t Bb = sb + OFF_BH + (c & 1) * 16384;
#pragma unroll
        for (int ks = 0; ks < 4; ks++) {
            uint32_t a[4][4], b[8][2];
#pragma unroll
            for (int mt = 0; mt < 4; mt++) {
                const int row = wm * 64 + mt * 16 + rA;
                const uint32_t addr = Ab + row * 128 + (((ks*2 + uA) ^ rl) << 4);
                LDMATRIX_X4(a[mt][0], a[mt][1], a[mt][2], a[mt][3], addr);
            }
#pragma unroll
            for (int p = 0; p < 4; p++) {
                const int row = wn * 64 + p * 16 + rB;
                const uint32_t addr = Bb + row * 128 + (((ks*2 + uB) ^ rl) << 4);
                LDMATRIX_X4(b[2*p][0], b[2*p][1], b[2*p+1][0], b[2*p+1][1], addr);
            }
#pragma unroll
            for (int mt = 0; mt < 4; mt++)
#pragma unroll
                for (int nt = 0; nt < 8; nt++)
                    MMA_F16(acc[mt][nt], a[mt], b[nt]);
        }
    }
#undef CONVERT

    // finish column terms: ct[j] = |X_j|^2 + w'_j^2 (exact fp32)
    float* bsqs = (float*)(smem + OFF_BSQ);
    float* cts  = (float*)(smem + OFF_CT);
    __syncthreads();
    bsqs[tid] = bsq;
    __syncthreads();
    if (tid < TILE_N) {
        const int j = n0 + tid;
        float v = INF_F;
        if (j < N_X) {
            const float wp = (g_wmax - w[j]) * (1.f / KCONST);
            v = bsqs[2*tid] + bsqs[2*tid + 1] + wp * wp;
            g_ct[j] = v;
        }
        cts[tid] = v;
    }
    __syncthreads();

#pragma unroll
    for (int mt = 0; mt < 4; mt++) {
        const int r0 = wm * 64 + mt * 16 + qr;
#pragma unroll
        for (int nt = 0; nt < 8; nt++) {
            const int col = wn * 64 + nt * 8 + 2 * qc;
            const int j   = n0 + col;
            if (j < N_X) {
                const float c0 = cts[col], c1 = cts[col + 1];
                float2 v0 = { c0 - 2.f * acc[mt][nt][0], c1 - 2.f * acc[mt][nt][1] };
                float2 v1 = { c0 - 2.f * acc[mt][nt][2], c1 - 2.f * acc[mt][nt][3] };
                *(float2*)&g_scores[(size_t)r0 * N_X + j]       = v0;
                *(float2*)&g_scores[(size_t)(r0 + 8) * N_X + j] = v1;
            }
        }
    }
}

// ---------------- kernel 2a: stage-1 selection (uint keys, vec loads) ------
__global__ __launch_bounds__(256) void k_top1()
{
    const int gw   = blockIdx.x * 8 + (threadIdx.x >> 5);  // 0..16383
    const int lane = threadIdx.x & 31;
    const int row  = gw >> 6;
    const int ws   = gw & 63;
    const uint32_t* srow = (const uint32_t*)(g_scores + (size_t)row * N_X);
    const int base = ws * SEG;
    const int end  = (base + SEG < N_X) ? base + SEG : N_X;   // multiple of 4

    uint32_t bv0 = ~0u, bv1 = ~0u, bv2 = ~0u, bv3 = ~0u;
    int      bi0 = 0,   bi1 = 0,   bi2 = 0,   bi3 = 0;

#define INS(v, i) do {                                                         \
    if ((v) < bv3) {                                                           \
        if ((v) < bv2) {                                                       \
            bv3 = bv2; bi3 = bi2;                                              \
            if ((v) < bv1) {                                                   \
                bv2 = bv1; bi2 = bi1;                                          \
                if ((v) < bv0) { bv1 = bv0; bi1 = bi0; bv0 = (v); bi0 = (i); } \
                else           { bv1 = (v); bi1 = (i); }                       \
            } else { bv2 = (v); bi2 = (i); }                                   \
        } else { bv3 = (v); bi3 = (i); }                                       \
    }                                                                          \
} while (0)

    for (int i = base + lane * 4; i < end; i += 128) {
        const uint4 u = *(const uint4*)(srow + i);
        INS(u.x, i);
        INS(u.y, i + 1);
        INS(u.z, i + 2);
        INS(u.w, i + 3);
    }
#undef INS

    unsigned long long k0 = ((unsigned long long)bv0 << 32) | (unsigned)bi0;
    unsigned long long k1 = ((unsigned long long)bv1 << 32) | (unsigned)bi1;
    unsigned long long k2 = ((unsigned long long)bv2 << 32) | (unsigned)bi2;
    unsigned long long k3 = ((unsigned long long)bv3 << 32) | (unsigned)bi3;

    unsigned long long mine = ~0ull;
#pragma unroll
    for (int r = 0; r < 8; r++) {
        unsigned long long k = k0;
#pragma unroll
        for (int o = 16; o > 0; o >>= 1) {
            const unsigned long long t = __shfl_xor_sync(0xffffffffu, k, o);
            if (t < k) k = t;
        }
        if (lane == r) mine = k;
        if (k == k0) { k0 = k1; k1 = k2; k2 = k3; k3 = ~0ull; }
    }
    if (lane < 8) g_cand1[(row * NSEG + ws) * 8 + lane] = mine;
}

// ---------------- kernel 2b: stage-2, rank-select top-32 of 512 -------------
__global__ __launch_bounds__(256) void k_top2()
{
    __shared__ unsigned long long c[512];
    const int row = blockIdx.x, tid = threadIdx.x;
    c[tid]       = g_cand1[row * 512 + tid];
    c[tid + 256] = g_cand1[row * 512 + tid + 256];
    __syncthreads();

    const unsigned long long v0 = c[tid], v1 = c[tid + 256];
    int r0 = 0, r1 = 0;
    for (int o = 0; o < 512; o++) {
        const unsigned long long x = c[o];
        r0 += (x < v0);
        r1 += (x < v1);
    }
    if (r0 < NCAND) g_cand[row * NCAND + r0] = (int)(unsigned)(v0 & 0xffffffffu);
    if (r1 < NCAND) g_cand[row * NCAND + r1] = (int)(unsigned)(v1 & 0xffffffffu);
}

// ---------------- kernel 3: fused exact rerank + L1 + max -------------------
__global__ __launch_bounds__(256) void k_post(
    const float* __restrict__ Xt, const float* __restrict__ X,
    const float* __restrict__ w, float* __restrict__ out)
{
    __shared__ float xts[DIM];
    __shared__ float d2s[NCAND];
    __shared__ float acts[NCAND];
    __shared__ int   idxs[NCAND];

    const int row  = blockIdx.x;
    const int tid  = threadIdx.x;
    const int warp = tid >> 5;
    const int lane = tid & 31;

    const float4* xtg = (const float4*)(Xt + (size_t)row * DIM);
    for (int i = tid; i < DIM / 4; i += 256) ((float4*)xts)[i] = xtg[i];
    __syncthreads();

    for (int t = warp; t < NCAND; t += 8) {
        const int j = g_cand[row * NCAND + t];
        const float4* xj  = (const float4*)(X + (size_t)j * DIM);
        const float4* xt4 = (const float4*)xts;
        float dot = 0.f, l1 = 0.f;
#pragma unroll 4
        for (int i = lane; i < DIM / 4; i += 32) {
            const float4 a = xj[i], b = xt4[i];
            dot = fmaf(a.x, b.x, fmaf(a.y, b.y, fmaf(a.z, b.z, fmaf(a.w, b.w, dot))));
            l1 += fabsf(a.x-b.x) + fabsf(a.y-b.y) + fabsf(a.z-b.z) + fabsf(a.w-b.w);
        }
#pragma unroll
        for (int o = 16; o > 0; o >>= 1) {
            dot += __shfl_xor_sync(0xffffffffu, dot, o);
            l1  += __shfl_xor_sync(0xffffffffu, l1,  o);
        }
        if (lane == 0) {
            d2s[t]  = g_ct[j] - 2.f * dot;
            acts[t] = w[j] - KCONST * l1;
            idxs[t] = j;
        }
    }
    __syncthreads();

    if (tid < 32) {
        const float v = d2s[tid];
        const int   j = idxs[tid];
        int rank = 0;
#pragma unroll
        for (int o = 0; o < NCAND; o++) {
            const float ov = __shfl_sync(0xffffffffu, v, o);
            const int   oj = __shfl_sync(0xffffffffu, j, o);
            rank += (ov < v || (ov == v && oj < j)) ? 1 : 0;
        }
        float a = (rank < TOPK) ? acts[tid] : -INF_F;
#pragma unroll
        for (int o = 16; o > 0; o >>= 1) a = fmaxf(a, __shfl_xor_sync(0xffffffffu, a, o));
        if (tid == 0) out[row] = a;
    }
}

// ---------------------------------------------------------------------------
extern "C" void kernel_launch(void* const* d_in, const int* in_sizes, int n_in,
                              void* d_out, int out_size)
{
    const float* Xt = (const float*)d_in[0];
    const float* X  = (const float*)d_in[1];
    const float* w  = (const float*)d_in[2];
    float* out = (float*)d_out;

    cudaFuncSetAttribute(k_score, cudaFuncAttributeMaxDynamicSharedMemorySize,
                         SMEM_TOTAL);

    k_wmax<<<1, 256>>>(w, N_X);
    k_cvtA<<<32, 256>>>(Xt);
    k_score<<<N_TILES, 256, SMEM_TOTAL>>>(X, w);
    k_top1<<<(M_Q * NSEG) / 8, 256>>>();
    k_top2<<<M_Q, 256>>>();
    k_post<<<M_Q, 256>>>(Xt, X, w, out);
}

// round 11
// speedup vs baseline: 10.0601x; 1.0345x over previous
#include <cuda_runtime.h>
#include <cuda_fp16.h>
#include <cstdint>
#include <cstddef>

#define M_Q    256
#define N_X    50000
#define DIM    3072
#define KCONST 750.0f
#define TOPK   16
#define NCAND  24

#define TILE_N  128
#define N_TILES 391              // ceil(50000/128)
#define KC      64               // k-chunk (elements)
#define CHUNKS  48               // 3072/64
#define A_STAGE    32768         // 256 rows x 128 B (f16), x3
#define BF32_STAGE 32768         // 128 rows x 256 B (fp32), x2
#define OFF_BF32 (3*A_STAGE)                  // 98304
#define OFF_BH   (OFF_BF32 + 2*BF32_STAGE)    // 163840 (f16 B tile x2)
#define OFF_CT   (OFF_BH + 2*16384)           // 196608
#define OFF_BSQ  (OFF_CT + 512)               // 197120
#define SMEM_TOTAL (OFF_BSQ + 1024)           // 198144

#define SEG    784               // 64*784 = 50176 >= 50000, 16B aligned
#define NSEG   64

#define INF_F __int_as_float(0x7f800000)

// ---------------- device scratch ----------------
__device__ float  g_wmax;
__device__ __half g_Xth[M_Q * DIM];           // f16 copy of X_tilde only
__device__ float  g_ct[N_X];                  // exact |X_j|^2 + w'_j^2
__device__ float  g_scores[(size_t)M_Q * N_X];
__device__ unsigned long long g_cand1[M_Q * NSEG * 8];

// ---------------- helpers ----------------
__device__ __forceinline__ uint32_t h2_bits(__half2 h) {
    return *reinterpret_cast<uint32_t*>(&h);
}
__device__ __forceinline__ uint32_t smem_u32(const void* p) {
    uint32_t a;
    asm("{ .reg .u64 t; cvta.to.shared.u64 t, %1; cvt.u32.u64 %0, t; }" : "=r"(a) : "l"(p));
    return a;
}
__device__ __forceinline__ void cp16(uint32_t dst, const void* src) {
    asm volatile("cp.async.cg.shared.global [%0], [%1], 16;"
                 :: "r"(dst), "l"(src) : "memory");
}
#define CP_COMMIT() asm volatile("cp.async.commit_group;" ::: "memory")
#define CP_WAIT1()  asm volatile("cp.async.wait_group 1;" ::: "memory")
#define CP_WAIT0()  asm volatile("cp.async.wait_group 0;" ::: "memory")

#define LDMATRIX_X4(r0, r1, r2, r3, addr)                                     \
    asm volatile("ldmatrix.sync.aligned.m8n8.x4.shared.b16 {%0,%1,%2,%3}, [%4];" \
                 : "=r"(r0), "=r"(r1), "=r"(r2), "=r"(r3) : "r"(addr))

#define MMA_F16(d, a, b)                                                       \
    asm volatile("mma.sync.aligned.m16n8k16.row.col.f32.f16.f16.f32 "          \
                 "{%0,%1,%2,%3}, {%4,%5,%6,%7}, {%8,%9}, {%0,%1,%2,%3};"       \
                 : "+f"((d)[0]), "+f"((d)[1]), "+f"((d)[2]), "+f"((d)[3])      \
                 : "r"((a)[0]), "r"((a)[1]), "r"((a)[2]), "r"((a)[3]),         \
                   "r"((b)[0]), "r"((b)[1]))

// ---------------- kernel 0: convert X_tilde + max(w) (merged) --------------
__global__ __launch_bounds__(256) void k_cvtw(
    const float* __restrict__ Xt, const float* __restrict__ w)
{
    if (blockIdx.x == 32) {      // wmax block
        __shared__ float sm[256];
        float v = -INF_F;
        for (int i = threadIdx.x; i < N_X; i += 256) v = fmaxf(v, w[i]);
        sm[threadIdx.x] = v;
        __syncthreads();
        for (int s = 128; s > 0; s >>= 1) {
            if (threadIdx.x < s) sm[threadIdx.x] = fmaxf(sm[threadIdx.x], sm[threadIdx.x + s]);
            __syncthreads();
        }
        if (threadIdx.x == 0) g_wmax = sm[0];
        return;
    }
    const int warp = blockIdx.x * 8 + (threadIdx.x >> 5);   // 0..255
    const int lane = threadIdx.x & 31;
    const float4* src = (const float4*)(Xt + (size_t)warp * DIM);
    uint4* dst = (uint4*)(g_Xth + (size_t)warp * DIM);
#pragma unroll 4
    for (int i = lane; i < DIM / 8; i += 32) {
        const float4 v0 = src[2*i], v1 = src[2*i + 1];
        uint4 o;
        o.x = h2_bits(__floats2half2_rn(v0.x, v0.y));
        o.y = h2_bits(__floats2half2_rn(v0.z, v0.w));
        o.z = h2_bits(__floats2half2_rn(v1.x, v1.y));
        o.w = h2_bits(__floats2half2_rn(v1.z, v1.w));
        dst[i] = o;
    }
}

// ---------------- kernel 1: fused f16 GEMM, overlapped B conversion --------
__device__ __forceinline__ void issueAB(uint32_t sb, int c,
                                        const float* __restrict__ X,
                                        int n0, int tid)
{
    const int k0 = c * KC;
    const uint32_t ab = sb + (c % 3) * A_STAGE;
    const uint32_t bb = sb + OFF_BF32 + (c & 1) * BF32_STAGE;
#pragma unroll
    for (int i = 0; i < 8; i++) {                 // A: 2048 16B units (f16)
        const int uid = tid + 256 * i;
        const int row = uid >> 3, u = uid & 7;
        cp16(ab + row * 128 + ((u ^ (row & 7)) << 4),
             g_Xth + (size_t)row * DIM + k0 + u * 8);
    }
#pragma unroll
    for (int i = 0; i < 8; i++) {                 // B: 2048 16B units (fp32)
        const int uid = tid + 256 * i;
        const int row = uid >> 4, u = uid & 15;
        const int gj  = n0 + row;
        cp16(bb + row * 256 + ((u ^ (row & 15)) << 4),
             X + (size_t)(gj < N_X ? gj : N_X - 1) * DIM + k0 + u * 4);
    }
}

__global__ __launch_bounds__(256, 1) void k_score(
    const float* __restrict__ X, const float* __restrict__ w)
{
    extern __shared__ char smem[];
    const uint32_t sb = smem_u32(smem);
    const int tid  = threadIdx.x;
    const int wid  = tid >> 5;
    const int lane = tid & 31;
    const int qr   = lane >> 2;
    const int qc   = lane & 3;
    const int wm   = wid >> 1;
    const int wn   = wid & 1;
    const int n0   = blockIdx.x * TILE_N;

    const int brow  = tid >> 1;
    const int bhalf = tid & 1;
    uint32_t ld_off[8], sts_off[4];
#pragma unroll
    for (int u = 0; u < 8; u++)
        ld_off[u] = brow * 256 + (((bhalf * 8 + u) ^ (brow & 15)) << 4);
#pragma unroll
    for (int q = 0; q < 4; q++)
        sts_off[q] = brow * 128 + (((bhalf * 4 + q) ^ (brow & 7)) << 4);

    const int sel = lane >> 3;
    const int rl  = lane & 7;
    const int rA  = ((sel & 1) << 3) + rl;
    const int uA  = sel >> 1;
    const int rB  = ((sel >> 1) << 3) + rl;
    const int uB  = sel & 1;

    float bsq = 0.f;

#define CONVERT(cc) do {                                                       \
        const char* bf = smem + OFF_BF32 + ((cc) & 1) * BF32_STAGE;            \
        char* bh = smem + OFF_BH + ((cc) & 1) * 16384;                         \
        _Pragma("unroll")                                                      \
        for (int q = 0; q < 4; q++) {                                          \
            const float4 v0 = *(const float4*)(bf + ld_off[2*q]);              \
            const float4 v1 = *(const float4*)(bf + ld_off[2*q + 1]);          \
            bsq = fmaf(v0.x, v0.x, fmaf(v0.y, v0.y,                            \
                  fmaf(v0.z, v0.z, fmaf(v0.w, v0.w, bsq))));                   \
            bsq = fmaf(v1.x, v1.x, fmaf(v1.y, v1.y,                            \
                  fmaf(v1.z, v1.z, fmaf(v1.w, v1.w, bsq))));                   \
            uint4 o;                                                           \
            o.x = h2_bits(__floats2half2_rn(v0.x, v0.y));                      \
            o.y = h2_bits(__floats2half2_rn(v0.z, v0.w));                      \
            o.z = h2_bits(__floats2half2_rn(v1.x, v1.y));                      \
            o.w = h2_bits(__floats2half2_rn(v1.z, v1.w));                      \
            *(uint4*)(bh + sts_off[q]) = o;                                    \
        }                                                                      \
    } while (0)

    issueAB(sb, 0, X, n0, tid); CP_COMMIT();
    issueAB(sb, 1, X, n0, tid); CP_COMMIT();
    CP_WAIT1();
    __syncthreads();
    CONVERT(0);

    float acc[4][8][4];
#pragma unroll
    for (int mt = 0; mt < 4; mt++)
#pragma unroll
        for (int nt = 0; nt < 8; nt++)
#pragma unroll
            for (int q = 0; q < 4; q++) acc[mt][nt][q] = 0.f;

    for (int c = 0; c < CHUNKS; c++) {
        CP_WAIT0();
        __syncthreads();

        if (c + 1 < CHUNKS) CONVERT(c + 1);          // overlaps with MMA(c)
        if (c + 2 < CHUNKS) { issueAB(sb, c + 2, X, n0, tid); CP_COMMIT(); }

        const uint32_t Ab = sb + (c % 3) * A_STAGE;
        const uint32_t Bb = sb + OFF_BH + (c & 1) * 16384;
#pragma unroll
        for (int ks = 0; ks < 4; ks++) {
            uint32_t a[4][4], b[8][2];
#pragma unroll
            for (int mt = 0; mt < 4; mt++) {
                const int row = wm * 64 + mt * 16 + rA;
                const uint32_t addr = Ab + row * 128 + (((ks*2 + uA) ^ rl) << 4);
                LDMATRIX_X4(a[mt][0], a[mt][1], a[mt][2], a[mt][3], addr);
            }
#pragma unroll
            for (int p = 0; p < 4; p++) {
                const int row = wn * 64 + p * 16 + rB;
                const uint32_t addr = Bb + row * 128 + (((ks*2 + uB) ^ rl) << 4);
                LDMATRIX_X4(b[2*p][0], b[2*p][1], b[2*p+1][0], b[2*p+1][1], addr);
            }
#pragma unroll
            for (int mt = 0; mt < 4; mt++)
#pragma unroll
                for (int nt = 0; nt < 8; nt++)
                    MMA_F16(acc[mt][nt], a[mt], b[nt]);
        }
    }
#undef CONVERT

    float* bsqs = (float*)(smem + OFF_BSQ);
    float* cts  = (float*)(smem + OFF_CT);
    __syncthreads();
    bsqs[tid] = bsq;
    __syncthreads();
    if (tid < TILE_N) {
        const int j = n0 + tid;
        float v = INF_F;
        if (j < N_X) {
            const float wp = (g_wmax - w[j]) * (1.f / KCONST);
            v = bsqs[2*tid] + bsqs[2*tid + 1] + wp * wp;
            g_ct[j] = v;
        }
        cts[tid] = v;
    }
    __syncthreads();

#pragma unroll
    for (int mt = 0; mt < 4; mt++) {
        const int r0 = wm * 64 + mt * 16 + qr;
#pragma unroll
        for (int nt = 0; nt < 8; nt++) {
            const int col = wn * 64 + nt * 8 + 2 * qc;
            const int j   = n0 + col;
            if (j < N_X) {
                const float c0 = cts[col], c1 = cts[col + 1];
                float2 v0 = { c0 - 2.f * acc[mt][nt][0], c1 - 2.f * acc[mt][nt][1] };
                float2 v1 = { c0 - 2.f * acc[mt][nt][2], c1 - 2.f * acc[mt][nt][3] };
                *(float2*)&g_scores[(size_t)r0 * N_X + j]       = v0;
                *(float2*)&g_scores[(size_t)(r0 + 8) * N_X + j] = v1;
            }
        }
    }
}

// ---------------- kernel 2: stage-1 selection (min-filtered insertion) -----
__global__ __launch_bounds__(256) void k_top1()
{
    const int gw   = blockIdx.x * 8 + (threadIdx.x >> 5);  // 0..16383
    const int lane = threadIdx.x & 31;
    const int row  = gw >> 6;
    const int ws   = gw & 63;
    const uint32_t* srow = (const uint32_t*)(g_scores + (size_t)row * N_X);
    const int base = ws * SEG;
    const int end  = (base + SEG < N_X) ? base + SEG : N_X;   // multiple of 4

    uint32_t bv0 = ~0u, bv1 = ~0u, bv2 = ~0u, bv3 = ~0u;
    int      bi0 = 0,   bi1 = 0,   bi2 = 0,   bi3 = 0;

#define INS(v, i) do {                                                         \
    if ((v) < bv3) {                                                           \
        if ((v) < bv2) {                                                       \
            bv3 = bv2; bi3 = bi2;                                              \
            if ((v) < bv1) {                                                   \
                bv2 = bv1; bi2 = bi1;                                          \
                if ((v) < bv0) { bv1 = bv0; bi1 = bi0; bv0 = (v); bi0 = (i); } \
                else           { bv1 = (v); bi1 = (i); }                       \
            } else { bv2 = (v); bi2 = (i); }                                   \
        } else { bv3 = (v); bi3 = (i); }                                       \
    }                                                                          \
} while (0)

    for (int i = base + lane * 4; i < end; i += 128) {
        const uint4 u = *(const uint4*)(srow + i);
        const uint32_t m = min(min(u.x, u.y), min(u.z, u.w));
        if (m < bv3) {                      // fast-path filter
            INS(u.x, i);
            INS(u.y, i + 1);
            INS(u.z, i + 2);
            INS(u.w, i + 3);
        }
    }
#undef INS

    unsigned long long k0 = ((unsigned long long)bv0 << 32) | (unsigned)bi0;
    unsigned long long k1 = ((unsigned long long)bv1 << 32) | (unsigned)bi1;
    unsigned long long k2 = ((unsigned long long)bv2 << 32) | (unsigned)bi2;
    unsigned long long k3 = ((unsigned long long)bv3 << 32) | (unsigned)bi3;

    unsigned long long mine = ~0ull;
#pragma unroll
    for (int r = 0; r < 8; r++) {
        unsigned long long k = k0;
#pragma unroll
        for (int o = 16; o > 0; o >>= 1) {
            const unsigned long long t = __shfl_xor_sync(0xffffffffu, k, o);
            if (t < k) k = t;
        }
        if (lane == r) mine = k;
        if (k == k0) { k0 = k1; k1 = k2; k2 = k3; k3 = ~0ull; }
    }
    if (lane < 8) g_cand1[(row * NSEG + ws) * 8 + lane] = mine;
}

// ---------------- kernel 3: stage-2 select + exact rerank + L1 + max --------
__global__ __launch_bounds__(256) void k_post(
    const float* __restrict__ Xt, const float* __restrict__ X,
    const float* __restrict__ w, float* __restrict__ out)
{
    __shared__ unsigned long long cbuf[512];
    __shared__ int   cand[NCAND];
    __shared__ float xts[DIM];
    __shared__ float d2s[NCAND];
    __shared__ float acts[NCAND];

    const int row  = blockIdx.x;
    const int tid  = threadIdx.x;
    const int warp = tid >> 5;
    const int lane = tid & 31;

    // stage 2: rank-select top-NCAND of 512 stage-1 candidates
    cbuf[tid]       = g_cand1[row * 512 + tid];
    cbuf[tid + 256] = g_cand1[row * 512 + tid + 256];
    __syncthreads();
    {
        const unsigned long long v0 = cbuf[tid], v1 = cbuf[tid + 256];
        int r0 = 0, r1 = 0;
        for (int o = 0; o < 512; o++) {
            const unsigned long long x = cbuf[o];
            r0 += (x < v0);
            r1 += (x < v1);
        }
        if (r0 < NCAND) cand[r0] = (int)(unsigned)(v0 & 0xffffffffu);
        if (r1 < NCAND) cand[r1] = (int)(unsigned)(v1 & 0xffffffffu);
    }

    // stage query row
    const float4* xtg = (const float4*)(Xt + (size_t)row * DIM);
    for (int i = tid; i < DIM / 4; i += 256) ((float4*)xts)[i] = xtg[i];
    __syncthreads();

    // exact fp32 d2 + L1 activation per candidate (one warp each)
    for (int t = warp; t < NCAND; t += 8) {
        const int j = cand[t];
        const float4* xj  = (const float4*)(X + (size_t)j * DIM);
        const float4* xt4 = (const float4*)xts;
        float dot = 0.f, l1 = 0.f;
#pragma unroll 4
        for (int i = lane; i < DIM / 4; i += 32) {
            const float4 a = xj[i], b = xt4[i];
            dot = fmaf(a.x, b.x, fmaf(a.y, b.y, fmaf(a.z, b.z, fmaf(a.w, b.w, dot))));
            l1 += fabsf(a.x-b.x) + fabsf(a.y-b.y) + fabsf(a.z-b.z) + fabsf(a.w-b.w);
        }
#pragma unroll
        for (int o = 16; o > 0; o >>= 1) {
            dot += __shfl_xor_sync(0xffffffffu, dot, o);
            l1  += __shfl_xor_sync(0xffffffffu, l1,  o);
        }
        if (lane == 0) {
            d2s[t]  = g_ct[j] - 2.f * dot;
            acts[t] = w[j] - KCONST * l1;
        }
    }
    __syncthreads();

    // exact top-16 by d2 (reference tie-break), max activation among them
    if (tid < 32) {
        const float v = (tid < NCAND) ? d2s[tid] : INF_F;
        const int   j = (tid < NCAND) ? cand[tid] : 0x7fffffff;
        int rank = 0;
#pragma unroll
        for (int o = 0; o < 32; o++) {
            const float ov = __shfl_sync(0xffffffffu, v, o);
            const int   oj = __shfl_sync(0xffffffffu, j, o);
            rank += (ov < v || (ov == v && oj < j)) ? 1 : 0;
        }
        float a = (rank < TOPK && tid < NCAND) ? acts[tid] : -INF_F;
#pragma unroll
        for (int o = 16; o > 0; o >>= 1) a = fmaxf(a, __shfl_xor_sync(0xffffffffu, a, o));
        if (tid == 0) out[row] = a;
    }
}

// ---------------------------------------------------------------------------
extern "C" void kernel_launch(void* const* d_in, const int* in_sizes, int n_in,
                              void* d_out, int out_size)
{
    const float* Xt = (const float*)d_in[0];
    const float* X  = (const float*)d_in[1];
    const float* w  = (const float*)d_in[2];
    float* out = (float*)d_out;

    cudaFuncSetAttribute(k_score, cudaFuncAttributeMaxDynamicSharedMemorySize,
                         SMEM_TOTAL);

    k_cvtw<<<33, 256>>>(Xt, w);
    k_score<<<N_TILES, 256, SMEM_TOTAL>>>(X, w);
    k_top1<<<(M_Q * NSEG) / 8, 256>>>();
    k_post<<<M_Q, 256>>>(Xt, X, w, out);
}

// round 12
// speedup vs baseline: 10.9156x; 1.0850x over previous
#include <cuda_runtime.h>
#include <cuda_fp16.h>
#include <cstdint>
#include <cstddef>

#define M_Q    256
#define N_X    50000
#define DIM    3072
#define KCONST 750.0f
#define TOPK   16
#define NCAND  24

#define TILE_N  128
#define N_TILES 391              // ceil(50000/128)
#define KC      64               // k-chunk (elements)
#define CHUNKS  48               // 3072/64
#define A_STAGE    32768         // 256 rows x 128 B (f16), x3
#define BF32_STAGE 32768         // 128 rows x 256 B (fp32), x2
#define OFF_BF32 (3*A_STAGE)                  // 98304
#define OFF_BH   (OFF_BF32 + 2*BF32_STAGE)    // 163840 (f16 B tile x2)
#define OFF_CT   (OFF_BH + 2*16384)           // 196608
#define OFF_BSQ  (OFF_CT + 512)               // 197120
#define SMEM_TOTAL (OFF_BSQ + 1024)           // 198144

#define SEG    1568              // 32*1568 = 50176 >= 50000, 16B aligned
#define NSEG   32

#define INF_F __int_as_float(0x7f800000)

// ---------------- device scratch ----------------
__device__ float  g_wmax;
__device__ __half g_Xth[M_Q * DIM];           // f16 copy of X_tilde only
__device__ float  g_ct[N_X];                  // exact |X_j|^2 + w'_j^2
__device__ float  g_scores[(size_t)M_Q * N_X];
__device__ unsigned long long g_cand1[M_Q * NSEG * 8];

// ---------------- helpers ----------------
__device__ __forceinline__ uint32_t h2_bits(__half2 h) {
    return *reinterpret_cast<uint32_t*>(&h);
}
__device__ __forceinline__ uint32_t smem_u32(const void* p) {
    uint32_t a;
    asm("{ .reg .u64 t; cvta.to.shared.u64 t, %1; cvt.u32.u64 %0, t; }" : "=r"(a) : "l"(p));
    return a;
}
__device__ __forceinline__ void cp16(uint32_t dst, const void* src) {
    asm volatile("cp.async.cg.shared.global [%0], [%1], 16;"
                 :: "r"(dst), "l"(src) : "memory");
}
#define CP_COMMIT() asm volatile("cp.async.commit_group;" ::: "memory")
#define CP_WAIT1()  asm volatile("cp.async.wait_group 1;" ::: "memory")
#define CP_WAIT0()  asm volatile("cp.async.wait_group 0;" ::: "memory")

#define LDMATRIX_X4(r0, r1, r2, r3, addr)                                     \
    asm volatile("ldmatrix.sync.aligned.m8n8.x4.shared.b16 {%0,%1,%2,%3}, [%4];" \
                 : "=r"(r0), "=r"(r1), "=r"(r2), "=r"(r3) : "r"(addr))

#define MMA_F16(d, a, b)                                                       \
    asm volatile("mma.sync.aligned.m16n8k16.row.col.f32.f16.f16.f32 "          \
                 "{%0,%1,%2,%3}, {%4,%5,%6,%7}, {%8,%9}, {%0,%1,%2,%3};"       \
                 : "+f"((d)[0]), "+f"((d)[1]), "+f"((d)[2]), "+f"((d)[3])      \
                 : "r"((a)[0]), "r"((a)[1]), "r"((a)[2]), "r"((a)[3]),         \
                   "r"((b)[0]), "r"((b)[1]))

// ---------------- kernel 0: convert X_tilde + max(w) (merged) --------------
__global__ __launch_bounds__(256) void k_cvtw(
    const float* __restrict__ Xt, const float* __restrict__ w)
{
    if (blockIdx.x == 32) {      // wmax block
        __shared__ float sm[256];
        float v = -INF_F;
        for (int i = threadIdx.x; i < N_X; i += 256) v = fmaxf(v, w[i]);
        sm[threadIdx.x] = v;
        __syncthreads();
        for (int s = 128; s > 0; s >>= 1) {
            if (threadIdx.x < s) sm[threadIdx.x] = fmaxf(sm[threadIdx.x], sm[threadIdx.x + s]);
            __syncthreads();
        }
        if (threadIdx.x == 0) g_wmax = sm[0];
        return;
    }
    const int warp = blockIdx.x * 8 + (threadIdx.x >> 5);   // 0..255
    const int lane = threadIdx.x & 31;
    const float4* src = (const float4*)(Xt + (size_t)warp * DIM);
    uint4* dst = (uint4*)(g_Xth + (size_t)warp * DIM);
#pragma unroll 4
    for (int i = lane; i < DIM / 8; i += 32) {
        const float4 v0 = src[2*i], v1 = src[2*i + 1];
        uint4 o;
        o.x = h2_bits(__floats2half2_rn(v0.x, v0.y));
        o.y = h2_bits(__floats2half2_rn(v0.z, v0.w));
        o.z = h2_bits(__floats2half2_rn(v1.x, v1.y));
        o.w = h2_bits(__floats2half2_rn(v1.z, v1.w));
        dst[i] = o;
    }
}

// ---------------- kernel 1: fused f16 GEMM, overlapped B conversion --------
__device__ __forceinline__ void issueAB(uint32_t sb, int c,
                                        const float* __restrict__ X,
                                        int n0, int tid)
{
    const int k0 = c * KC;
    const uint32_t ab = sb + (c % 3) * A_STAGE;
    const uint32_t bb = sb + OFF_BF32 + (c & 1) * BF32_STAGE;
#pragma unroll
    for (int i = 0; i < 8; i++) {                 // A: 2048 16B units (f16)
        const int uid = tid + 256 * i;
        const int row = uid >> 3, u = uid & 7;
        cp16(ab + row * 128 + ((u ^ (row & 7)) << 4),
             g_Xth + (size_t)row * DIM + k0 + u * 8);
    }
#pragma unroll
    for (int i = 0; i < 8; i++) {                 // B: 2048 16B units (fp32)
        const int uid = tid + 256 * i;
        const int row = uid >> 4, u = uid & 15;
        const int gj  = n0 + row;
        cp16(bb + row * 256 + ((u ^ (row & 15)) << 4),
             X + (size_t)(gj < N_X ? gj : N_X - 1) * DIM + k0 + u * 4);
    }
}

__global__ __launch_bounds__(256, 1) void k_score(
    const float* __restrict__ X, const float* __restrict__ w)
{
    extern __shared__ char smem[];
    const uint32_t sb = smem_u32(smem);
    const int tid  = threadIdx.x;
    const int wid  = tid >> 5;
    const int lane = tid & 31;
    const int qr   = lane >> 2;
    const int qc   = lane & 3;
    const int wm   = wid >> 1;
    const int wn   = wid & 1;
    const int n0   = blockIdx.x * TILE_N;

    const int brow  = tid >> 1;
    const int bhalf = tid & 1;
    uint32_t ld_off[8], sts_off[4];
#pragma unroll
    for (int u = 0; u < 8; u++)
        ld_off[u] = brow * 256 + (((bhalf * 8 + u) ^ (brow & 15)) << 4);
#pragma unroll
    for (int q = 0; q < 4; q++)
        sts_off[q] = brow * 128 + (((bhalf * 4 + q) ^ (brow & 7)) << 4);

    const int sel = lane >> 3;
    const int rl  = lane & 7;
    const int rA  = ((sel & 1) << 3) + rl;
    const int uA  = sel >> 1;
    const int rB  = ((sel >> 1) << 3) + rl;
    const int uB  = sel & 1;

    float bsq = 0.f;

#define CONVERT(cc) do {                                                       \
        const char* bf = smem + OFF_BF32 + ((cc) & 1) * BF32_STAGE;            \
        char* bh = smem + OFF_BH + ((cc) & 1) * 16384;                         \
        _Pragma("unroll")                                                      \
        for (int q = 0; q < 4; q++) {                                          \
            const float4 v0 = *(const float4*)(bf + ld_off[2*q]);              \
            const float4 v1 = *(const float4*)(bf + ld_off[2*q + 1]);          \
            bsq = fmaf(v0.x, v0.x, fmaf(v0.y, v0.y,                            \
                  fmaf(v0.z, v0.z, fmaf(v0.w, v0.w, bsq))));                   \
            bsq = fmaf(v1.x, v1.x, fmaf(v1.y, v1.y,                            \
                  fmaf(v1.z, v1.z, fmaf(v1.w, v1.w, bsq))));                   \
            uint4 o;                                                           \
            o.x = h2_bits(__floats2half2_rn(v0.x, v0.y));                      \
            o.y = h2_bits(__floats2half2_rn(v0.z, v0.w));                      \
            o.z = h2_bits(__floats2half2_rn(v1.x, v1.y));                      \
            o.w = h2_bits(__floats2half2_rn(v1.z, v1.w));                      \
            *(uint4*)(bh + sts_off[q]) = o;                                    \
        }                                                                      \
    } while (0)

    issueAB(sb, 0, X, n0, tid); CP_COMMIT();
    issueAB(sb, 1, X, n0, tid); CP_COMMIT();
    CP_WAIT1();
    __syncthreads();
    CONVERT(0);

    float acc[4][8][4];
#pragma unroll
    for (int mt = 0; mt < 4; mt++)
#pragma unroll
        for (int nt = 0; nt < 8; nt++)
#pragma unroll
            for (int q = 0; q < 4; q++) acc[mt][nt][q] = 0.f;

    for (int c = 0; c < CHUNKS; c++) {
        CP_WAIT0();
        __syncthreads();

        if (c + 1 < CHUNKS) CONVERT(c + 1);          // overlaps with MMA(c)
        if (c + 2 < CHUNKS) { issueAB(sb, c + 2, X, n0, tid); CP_COMMIT(); }

        const uint32_t Ab = sb + (c % 3) * A_STAGE;
        const uint32_t Bb = sb + OFF_BH + (c & 1) * 16384;
#pragma unroll
        for (int ks = 0; ks < 4; ks++) {
            uint32_t a[4][4], b[8][2];
#pragma unroll
            for (int mt = 0; mt < 4; mt++) {
                const int row = wm * 64 + mt * 16 + rA;
                const uint32_t addr = Ab + row * 128 + (((ks*2 + uA) ^ rl) << 4);
                LDMATRIX_X4(a[mt][0], a[mt][1], a[mt][2], a[mt][3], addr);
            }
#pragma unroll
            for (int p = 0; p < 4; p++) {
                const int row = wn * 64 + p * 16 + rB;
                const uint32_t addr = Bb + row * 128 + (((ks*2 + uB) ^ rl) << 4);
                LDMATRIX_X4(b[2*p][0], b[2*p][1], b[2*p+1][0], b[2*p+1][1], addr);
            }
#pragma unroll
            for (int mt = 0; mt < 4; mt++)
#pragma unroll
                for (int nt = 0; nt < 8; nt++)
                    MMA_F16(acc[mt][nt], a[mt], b[nt]);
        }
    }
#undef CONVERT

    float* bsqs = (float*)(smem + OFF_BSQ);
    float* cts  = (float*)(smem + OFF_CT);
    __syncthreads();
    bsqs[tid] = bsq;
    __syncthreads();
    if (tid < TILE_N) {
        const int j = n0 + tid;
        float v = INF_F;
        if (j < N_X) {
            const float wp = (g_wmax - w[j]) * (1.f / KCONST);
            v = bsqs[2*tid] + bsqs[2*tid + 1] + wp * wp;
            g_ct[j] = v;
        }
        cts[tid] = v;
    }
    __syncthreads();

#pragma unroll
    for (int mt = 0; mt < 4; mt++) {
        const int r0 = wm * 64 + mt * 16 + qr;
#pragma unroll
        for (int nt = 0; nt < 8; nt++) {
            const int col = wn * 64 + nt * 8 + 2 * qc;
            const int j   = n0 + col;
            if (j < N_X) {
                const float c0 = cts[col], c1 = cts[col + 1];
                float2 v0 = { c0 - 2.f * acc[mt][nt][0], c1 - 2.f * acc[mt][nt][1] };
                float2 v1 = { c0 - 2.f * acc[mt][nt][2], c1 - 2.f * acc[mt][nt][3] };
                *(float2*)&g_scores[(size_t)r0 * N_X + j]       = v0;
                *(float2*)&g_scores[(size_t)(r0 + 8) * N_X + j] = v1;
            }
        }
    }
}

// ---------------- kernel 2: stage-1 selection (min-filtered insertion) -----
__global__ __launch_bounds__(256) void k_top1()
{
    const int gw   = blockIdx.x * 8 + (threadIdx.x >> 5);  // 0..8191
    const int lane = threadIdx.x & 31;
    const int row  = gw >> 5;          // /NSEG
    const int ws   = gw & 31;          // %NSEG
    const uint32_t* srow = (const uint32_t*)(g_scores + (size_t)row * N_X);
    const int base = ws * SEG;
    const int end  = (base + SEG < N_X) ? base + SEG : N_X;   // multiple of 4

    uint32_t bv0 = ~0u, bv1 = ~0u, bv2 = ~0u, bv3 = ~0u;
    int      bi0 = 0,   bi1 = 0,   bi2 = 0,   bi3 = 0;

#define INS(v, i) do {                                                         \
    if ((v) < bv3) {                                                           \
        if ((v) < bv2) {                                                       \
            bv3 = bv2; bi3 = bi2;                                              \
            if ((v) < bv1) {                                                   \
                bv2 = bv1; bi2 = bi1;                                          \
                if ((v) < bv0) { bv1 = bv0; bi1 = bi0; bv0 = (v); bi0 = (i); } \
                else           { bv1 = (v); bi1 = (i); }                       \
            } else { bv2 = (v); bi2 = (i); }                                   \
        } else { bv3 = (v); bi3 = (i); }                                       \
    }                                                                          \
} while (0)

    for (int i = base + lane * 4; i < end; i += 128) {
        const uint4 u = *(const uint4*)(srow + i);
        const uint32_t m = min(min(u.x, u.y), min(u.z, u.w));
        if (m < bv3) {                      // fast-path filter
            INS(u.x, i);
            INS(u.y, i + 1);
            INS(u.z, i + 2);
            INS(u.w, i + 3);
        }
    }
#undef INS

    unsigned long long k0 = ((unsigned long long)bv0 << 32) | (unsigned)bi0;
    unsigned long long k1 = ((unsigned long long)bv1 << 32) | (unsigned)bi1;
    unsigned long long k2 = ((unsigned long long)bv2 << 32) | (unsigned)bi2;
    unsigned long long k3 = ((unsigned long long)bv3 << 32) | (unsigned)bi3;

    unsigned long long mine = ~0ull;
#pragma unroll
    for (int r = 0; r < 8; r++) {
        unsigned long long k = k0;
#pragma unroll
        for (int o = 16; o > 0; o >>= 1) {
            const unsigned long long t = __shfl_xor_sync(0xffffffffu, k, o);
            if (t < k) k = t;
        }
        if (lane == r) mine = k;
        if (k == k0) { k0 = k1; k1 = k2; k2 = k3; k3 = ~0ull; }
    }
    if (lane < 8) g_cand1[(row * NSEG + ws) * 8 + lane] = mine;
}

// ---------------- kernel 3: stage-2 select + exact rerank + L1 + max --------
// 768 threads = 24 warps: one warp per candidate (single gather pass).
__global__ __launch_bounds__(768) void k_post(
    const float* __restrict__ Xt, const float* __restrict__ X,
    const float* __restrict__ w, float* __restrict__ out)
{
    __shared__ unsigned long long cbuf[256];    // NSEG*8
    __shared__ int   cand[NCAND];
    __shared__ float xts[DIM];
    __shared__ float d2s[NCAND];
    __shared__ float acts[NCAND];

    const int row  = blockIdx.x;
    const int tid  = threadIdx.x;
    const int warp = tid >> 5;
    const int lane = tid & 31;

    // stage 2: rank-select top-NCAND of 256 stage-1 candidates
    if (tid < 256) cbuf[tid] = g_cand1[row * 256 + tid];
    __syncthreads();
    if (tid < 256) {
        const unsigned long long v0 = cbuf[tid];
        int r0 = 0;
        for (int o = 0; o < 256; o++) r0 += (cbuf[o] < v0);
        if (r0 < NCAND) cand[r0] = (int)(unsigned)(v0 & 0xffffffffu);
    }

    // stage query row (all 768 threads)
    const float4* xtg = (const float4*)(Xt + (size_t)row * DIM);
    for (int i = tid; i < DIM / 4; i += 768) ((float4*)xts)[i] = xtg[i];
    __syncthreads();

    // exact fp32 d2 + L1 activation: one warp per candidate
    if (warp < NCAND) {
        const int j = cand[warp];
        const float4* xj  = (const float4*)(X + (size_t)j * DIM);
        const float4* xt4 = (const float4*)xts;
        float dot = 0.f, l1 = 0.f;
#pragma unroll 4
        for (int i = lane; i < DIM / 4; i += 32) {
            const float4 a = xj[i], b = xt4[i];
            dot = fmaf(a.x, b.x, fmaf(a.y, b.y, fmaf(a.z, b.z, fmaf(a.w, b.w, dot))));
            l1 += fabsf(a.x-b.x) + fabsf(a.y-b.y) + fabsf(a.z-b.z) + fabsf(a.w-b.w);
        }
#pragma unroll
        for (int o = 16; o > 0; o >>= 1) {
            dot += __shfl_xor_sync(0xffffffffu, dot, o);
            l1  += __shfl_xor_sync(0xffffffffu, l1,  o);
        }
        if (lane == 0) {
            d2s[warp]  = g_ct[j] - 2.f * dot;
            acts[warp] = w[j] - KCONST * l1;
        }
    }
    __syncthreads();

    // exact top-16 by d2 (reference tie-break), max activation among them
    if (tid < 32) {
        const float v = (tid < NCAND) ? d2s[tid] : INF_F;
        const int   j = (tid < NCAND) ? cand[tid] : 0x7fffffff;
        int rank = 0;
#pragma unroll
        for (int o = 0; o < 32; o++) {
            const float ov = __shfl_sync(0xffffffffu, v, o);
            const int   oj = __shfl_sync(0xffffffffu, j, o);
            rank += (ov < v || (ov == v && oj < j)) ? 1 : 0;
        }
        float a = (rank < TOPK && tid < NCAND) ? acts[tid] : -INF_F;
#pragma unroll
        for (int o = 16; o > 0; o >>= 1) a = fmaxf(a, __shfl_xor_sync(0xffffffffu, a, o));
        if (tid == 0) out[row] = a;
    }
}

// ---------------------------------------------------------------------------
extern "C" void kernel_launch(void* const* d_in, const int* in_sizes, int n_in,
                              void* d_out, int out_size)
{
    const float* Xt = (const float*)d_in[0];
    const float* X  = (const float*)d_in[1];
    const float* w  = (const float*)d_in[2];
    float* out = (float*)d_out;

    cudaFuncSetAttribute(k_score, cudaFuncAttributeMaxDynamicSharedMemorySize,
                         SMEM_TOTAL);

    k_cvtw<<<33, 256>>>(Xt, w);
    k_score<<<N_TILES, 256, SMEM_TOTAL>>>(X, w);
    k_top1<<<(M_Q * NSEG) / 8, 256>>>();
    k_post<<<M_Q, 768>>>(Xt, X, w, out);
}